// round 3
// baseline (speedup 1.0000x reference)
#include <cuda_runtime.h>
#include <cuda_bf16.h>
#include <math.h>

// Problem constants
#define SS   512
#define BB   32
#define DD   1024
#define HH   1024
#define G4H  4096          // 4*H
#define BH   (BB*HH)       // 32768

typedef unsigned long long ull;

// packed fp32x2 FMA (Blackwell): d.xy += a.xy * b.xy
#define FFMA2(d, a, b) asm("fma.rn.f32x2 %0, %1, %2, %0;" : "+l"(d) : "l"(a), "l"(b))
// pack {s, s} into a 64-bit f32x2
#define PACK2(d, s) asm("mov.b64 %0, {%1, %1};" : "=l"(d) : "r"(s))

// ---------------- scratch: X = layer_input @ U^T + bias  [S*B, 4H] ----------
__device__ float g_X[(size_t)SS * BB * G4H];   // 256 MB

// ============================================================================
// Kernel A: SGEMM (NT): X[m][n] = sum_k A[m][k] * W[n][k] + bih[n] + bhh[n]
//   128x128 tile, BK=16, 256 threads, 8x8 per thread, f32x2 inner product
//   (pairs over the n dimension; Bs pairs are contiguous in smem).
// ============================================================================
__global__ void __launch_bounds__(256) gemm_x_kernel(
    const float* __restrict__ A,
    const float* __restrict__ W,
    const float* __restrict__ bih,
    const float* __restrict__ bhh,
    float* __restrict__ X)
{
    __shared__ float As[16][128];
    __shared__ float Bs[16][128];

    const int bm = blockIdx.y * 128;
    const int bn = blockIdx.x * 128;
    const int tid = threadIdx.x;
    const int tx = tid & 15;        // 0..15 -> columns
    const int ty = tid >> 4;        // 0..15 -> rows

    const int lr = tid >> 2;        // 0..63 row within tile (and +64)
    const int lc = (tid & 3) * 4;   // k offset 0,4,8,12

    const float* Aptr = A + (size_t)(bm + lr) * DD + lc;
    const float* Wptr = W + (size_t)(bn + lr) * DD + lc;

    ull acc2[8][4];
    #pragma unroll
    for (int i = 0; i < 8; i++)
        #pragma unroll
        for (int j = 0; j < 4; j++) acc2[i][j] = 0ULL;

    for (int k0 = 0; k0 < DD; k0 += 16) {
        float4 a0 = *(const float4*)(Aptr + k0);
        float4 a1 = *(const float4*)(Aptr + (size_t)64 * DD + k0);
        float4 w0 = *(const float4*)(Wptr + k0);
        float4 w1 = *(const float4*)(Wptr + (size_t)64 * DD + k0);

        __syncthreads();
        As[lc+0][lr]    = a0.x; As[lc+1][lr]    = a0.y; As[lc+2][lr]    = a0.z; As[lc+3][lr]    = a0.w;
        As[lc+0][lr+64] = a1.x; As[lc+1][lr+64] = a1.y; As[lc+2][lr+64] = a1.z; As[lc+3][lr+64] = a1.w;
        Bs[lc+0][lr]    = w0.x; Bs[lc+1][lr]    = w0.y; Bs[lc+2][lr]    = w0.z; Bs[lc+3][lr]    = w0.w;
        Bs[lc+0][lr+64] = w1.x; Bs[lc+1][lr+64] = w1.y; Bs[lc+2][lr+64] = w1.z; Bs[lc+3][lr+64] = w1.w;
        __syncthreads();

        #pragma unroll
        for (int kk = 0; kk < 16; kk++) {
            float ar[8];
            *(float4*)&ar[0] = *(const float4*)&As[kk][ty * 4];
            *(float4*)&ar[4] = *(const float4*)&As[kk][ty * 4 + 64];
            ulonglong2 b0 = *(const ulonglong2*)&Bs[kk][tx * 4];
            ulonglong2 b1 = *(const ulonglong2*)&Bs[kk][tx * 4 + 64];
            ull br2[4] = {b0.x, b0.y, b1.x, b1.y};
            ull ap[8];
            #pragma unroll
            for (int i = 0; i < 8; i++) PACK2(ap[i], __float_as_uint(ar[i]));
            #pragma unroll
            for (int i = 0; i < 8; i++)
                #pragma unroll
                for (int j = 0; j < 4; j++)
                    FFMA2(acc2[i][j], ap[i], br2[j]);
        }
    }

    // epilogue with fused bias
    const int gn0 = bn + tx * 4;
    float b0v[4], b1v[4];
    #pragma unroll
    for (int j = 0; j < 4; j++) {
        b0v[j] = bih[gn0 + j]      + bhh[gn0 + j];
        b1v[j] = bih[gn0 + 64 + j] + bhh[gn0 + 64 + j];
    }

    #pragma unroll
    for (int ii = 0; ii < 8; ii++) {
        int m = bm + ty * 4 + ((ii < 4) ? ii : (60 + ii));  // +64 offset for ii>=4
        float2 f0 = *(float2*)&acc2[ii][0];
        float2 f1 = *(float2*)&acc2[ii][1];
        float2 f2 = *(float2*)&acc2[ii][2];
        float2 f3 = *(float2*)&acc2[ii][3];
        float4 o0, o1;
        o0.x = f0.x + b0v[0]; o0.y = f0.y + b0v[1];
        o0.z = f1.x + b0v[2]; o0.w = f1.y + b0v[3];
        o1.x = f2.x + b1v[0]; o1.y = f2.y + b1v[1];
        o1.z = f3.x + b1v[2]; o1.w = f3.y + b1v[3];
        *(float4*)&X[(size_t)m * G4H + gn0]      = o0;
        *(float4*)&X[(size_t)m * G4H + gn0 + 64] = o1;
    }
}

// ============================================================================
// Kernel B: one LSTM step, f32x2 packed (pairs over k), split-K=4 in-CTA.
//   grid = 128 CTAs x 256 threads. CTA cb owns cols [cb*8, cb*8+8) of each
//   gate -> 32 gate rows x 32 batches.
//   Thread: kg = tid>>6 (k-chunk of 256), t = tid&63: rg = t>>3 -> 4 rows,
//   bg = t&7 -> 4 batches. 16 f32x2 accumulators, 8 LDG.128 + 32 FFMA2/iter.
//   h is read directly from the previous step's output (L1-resident chunk).
// ============================================================================
__global__ void __launch_bounds__(256) lstm_step_kernel(
    const float* __restrict__ Xg,     // [B][4096] for this step
    const float* __restrict__ h_prev, // [B][1024]
    const float* __restrict__ c_prev, // [B][1024]
    const float* __restrict__ V,      // [4096][1024]
    float* __restrict__ h_out1,
    float* __restrict__ h_out2,
    float* __restrict__ c_out)
{
    __shared__ float pbuf[4][32][36];   // [kg][local row][batch] partials

    const int tid = threadIdx.x;
    const int cb  = blockIdx.x;

    const int kg = tid >> 6;        // 0..3
    const int t  = tid & 63;
    const int rg = t >> 3;          // 0..7 -> local rows rg*4..rg*4+3
    const int bg = t & 7;           // 0..7 -> batches bg*4..bg*4+3
    const int k0 = kg * 256;

    // local row lr = rg*4+i ; gate = lr>>3 = rg>>1 ; c = lr&7
    const int gate0 = rg >> 1;
    const int c0    = (rg & 1) * 4;                  // +i
    const size_t row0 = (size_t)gate0 * HH + cb * 8 + c0;  // rows row0..row0+3

    const float* vp = V + row0 * HH + k0;
    const float* hp = h_prev + (size_t)(bg * 4) * HH + k0;

    ull acc2[4][4];
    #pragma unroll
    for (int i = 0; i < 4; i++)
        #pragma unroll
        for (int j = 0; j < 4; j++) acc2[i][j] = 0ULL;

    #pragma unroll 2
    for (int kk = 0; kk < 256; kk += 4) {
        ulonglong2 hv[4], vv[4];
        #pragma unroll
        for (int j = 0; j < 4; j++)
            hv[j] = *(const ulonglong2*)(hp + (size_t)j * HH + kk);
        #pragma unroll
        for (int i = 0; i < 4; i++)
            vv[i] = *(const ulonglong2*)(vp + (size_t)i * HH + kk);
        #pragma unroll
        for (int i = 0; i < 4; i++)
            #pragma unroll
            for (int j = 0; j < 4; j++) {
                FFMA2(acc2[i][j], vv[i].x, hv[j].x);
                FFMA2(acc2[i][j], vv[i].y, hv[j].y);
            }
    }

    // reduce pair halves, write partials
    #pragma unroll
    for (int i = 0; i < 4; i++)
        #pragma unroll
        for (int j = 0; j < 4; j++) {
            float2 f = *(float2*)&acc2[i][j];
            pbuf[kg][rg * 4 + i][bg * 4 + j] = f.x + f.y;
        }
    __syncthreads();

    // combine: thread -> (c, b) cell
    const int c = tid >> 5;     // 0..7
    const int b = tid & 31;     // 0..31

    float gv4[4];
    #pragma unroll
    for (int g = 0; g < 4; g++) {
        int lr = g * 8 + c;
        float s = pbuf[0][lr][b] + pbuf[1][lr][b] + pbuf[2][lr][b] + pbuf[3][lr][b];
        s += __ldg(&Xg[(size_t)b * G4H + (size_t)g * HH + cb * 8 + c]);
        gv4[g] = s;
    }

    const float iv = 1.f / (1.f + __expf(-gv4[0]));
    const float fv = 1.f / (1.f + __expf(-gv4[1]));
    const float gg = tanhf(gv4[2]);
    const float ov = 1.f / (1.f + __expf(-gv4[3]));

    const int col = cb * 8 + c;
    const float cp = c_prev[(size_t)b * HH + col];
    const float cn = fv * cp + iv * gg;
    const float hn = ov * tanhf(cn);

    h_out1[(size_t)b * HH + col] = hn;
    h_out2[(size_t)b * HH + col] = hn;
    c_out[(size_t)b * HH + col]  = cn;
}

// final state copy: h_f = all_h[S-1], c_f = all_c[S-1]
__global__ void copy_final_kernel(const float* __restrict__ h_last,
                                  const float* __restrict__ c_last,
                                  float* __restrict__ h_f,
                                  float* __restrict__ c_f)
{
    int i = blockIdx.x * blockDim.x + threadIdx.x;
    if (i < BH) {
        h_f[i] = h_last[i];
        c_f[i] = c_last[i];
    }
}

// ============================================================================
// Launch
// ============================================================================
extern "C" void kernel_launch(void* const* d_in, const int* in_sizes, int n_in,
                              void* d_out, int out_size)
{
    const float* layer_input = (const float*)d_in[0];  // [S,B,D]
    const float* h_t         = (const float*)d_in[1];  // [B,H]
    const float* c_t         = (const float*)d_in[2];  // [B,H]
    const float* U           = (const float*)d_in[3];  // [4H,D]
    const float* V           = (const float*)d_in[4];  // [4H,H]
    const float* bih         = (const float*)d_in[5];  // [4H]
    const float* bhh         = (const float*)d_in[6];  // [4H]

    float* out = (float*)d_out;
    // output tuple: (all_h, h_f, c_f, all_h, all_c)
    float* all_h1 = out;
    float* h_f    = out + (size_t)SS * BH;
    float* c_f    = h_f + BH;
    float* all_h2 = c_f + BH;
    float* all_c  = all_h2 + (size_t)SS * BH;

    float* Xp = nullptr;
    cudaGetSymbolAddress((void**)&Xp, g_X);

    // Kernel A: input projection + bias
    dim3 gg(G4H / 128, (SS * BB) / 128);   // (32, 128)
    gemm_x_kernel<<<gg, 256>>>(layer_input, U, bih, bhh, Xp);

    // Kernel B: 512 sequential steps (stream-ordered)
    for (int s = 0; s < SS; s++) {
        const float* hp = (s == 0) ? h_t : all_h1 + (size_t)(s - 1) * BH;
        const float* cp = (s == 0) ? c_t : all_c  + (size_t)(s - 1) * BH;
        lstm_step_kernel<<<128, 256>>>(
            Xp + (size_t)s * BB * G4H, hp, cp, V,
            all_h1 + (size_t)s * BH,
            all_h2 + (size_t)s * BH,
            all_c  + (size_t)s * BH);
    }

    copy_final_kernel<<<(BH + 255) / 256, 256>>>(
        all_h1 + (size_t)(SS - 1) * BH,
        all_c  + (size_t)(SS - 1) * BH,
        h_f, c_f);
}

// round 4
// speedup vs baseline: 2.3655x; 2.3655x over previous
#include <cuda_runtime.h>
#include <cuda_bf16.h>
#include <math.h>

// Problem constants
#define SS   512
#define BB   32
#define DD   1024
#define HH   1024
#define G4H  4096          // 4*H
#define BH   (BB*HH)       // 32768

typedef unsigned long long ull;

// packed fp32x2 FMA (Blackwell): d.xy += a.xy * b.xy
#define FFMA2(d, a, b) asm("fma.rn.f32x2 %0, %1, %2, %0;" : "+l"(d) : "l"(a), "l"(b))

// ---------------- scratch: X = layer_input @ U^T + bias  [S*B, 4H] ----------
__device__ float g_X[(size_t)SS * BB * G4H];   // 256 MB

// ============================================================================
// Kernel A: SGEMM (NT): X[m][n] = sum_k A[m][k] * W[n][k] + bih[n] + bhh[n]
//   (proven R2 version, plain fp32)
// ============================================================================
__global__ void __launch_bounds__(256) gemm_x_kernel(
    const float* __restrict__ A,
    const float* __restrict__ W,
    const float* __restrict__ bih,
    const float* __restrict__ bhh,
    float* __restrict__ X)
{
    __shared__ float As[16][128];
    __shared__ float Bs[16][128];

    const int bm = blockIdx.y * 128;
    const int bn = blockIdx.x * 128;
    const int tid = threadIdx.x;
    const int tx = tid & 15;
    const int ty = tid >> 4;

    const int lr = tid >> 2;
    const int lc = (tid & 3) * 4;

    const float* Aptr = A + (size_t)(bm + lr) * DD + lc;
    const float* Wptr = W + (size_t)(bn + lr) * DD + lc;

    float acc[8][8];
    #pragma unroll
    for (int i = 0; i < 8; i++)
        #pragma unroll
        for (int j = 0; j < 8; j++) acc[i][j] = 0.f;

    for (int k0 = 0; k0 < DD; k0 += 16) {
        float4 a0 = *(const float4*)(Aptr + k0);
        float4 a1 = *(const float4*)(Aptr + (size_t)64 * DD + k0);
        float4 w0 = *(const float4*)(Wptr + k0);
        float4 w1 = *(const float4*)(Wptr + (size_t)64 * DD + k0);

        __syncthreads();
        As[lc+0][lr]    = a0.x; As[lc+1][lr]    = a0.y; As[lc+2][lr]    = a0.z; As[lc+3][lr]    = a0.w;
        As[lc+0][lr+64] = a1.x; As[lc+1][lr+64] = a1.y; As[lc+2][lr+64] = a1.z; As[lc+3][lr+64] = a1.w;
        Bs[lc+0][lr]    = w0.x; Bs[lc+1][lr]    = w0.y; Bs[lc+2][lr]    = w0.z; Bs[lc+3][lr]    = w0.w;
        Bs[lc+0][lr+64] = w1.x; Bs[lc+1][lr+64] = w1.y; Bs[lc+2][lr+64] = w1.z; Bs[lc+3][lr+64] = w1.w;
        __syncthreads();

        #pragma unroll
        for (int kk = 0; kk < 16; kk++) {
            float ar[8], br[8];
            *(float4*)&ar[0] = *(const float4*)&As[kk][ty * 4];
            *(float4*)&ar[4] = *(const float4*)&As[kk][ty * 4 + 64];
            *(float4*)&br[0] = *(const float4*)&Bs[kk][tx * 4];
            *(float4*)&br[4] = *(const float4*)&Bs[kk][tx * 4 + 64];
            #pragma unroll
            for (int i = 0; i < 8; i++)
                #pragma unroll
                for (int j = 0; j < 8; j++)
                    acc[i][j] += ar[i] * br[j];
        }
    }

    const int gn0 = bn + tx * 4;
    float b0[4], b1[4];
    #pragma unroll
    for (int j = 0; j < 4; j++) {
        b0[j] = bih[gn0 + j]      + bhh[gn0 + j];
        b1[j] = bih[gn0 + 64 + j] + bhh[gn0 + 64 + j];
    }

    #pragma unroll
    for (int ii = 0; ii < 8; ii++) {
        int m = bm + ty * 4 + ((ii < 4) ? ii : (60 + ii));
        float4 o0, o1;
        o0.x = acc[ii][0] + b0[0]; o0.y = acc[ii][1] + b0[1];
        o0.z = acc[ii][2] + b0[2]; o0.w = acc[ii][3] + b0[3];
        o1.x = acc[ii][4] + b1[0]; o1.y = acc[ii][5] + b1[1];
        o1.z = acc[ii][6] + b1[2]; o1.w = acc[ii][7] + b1[3];
        *(float4*)&X[(size_t)m * G4H + gn0]      = o0;
        *(float4*)&X[(size_t)m * G4H + gn0 + 64] = o1;
    }
}

// ============================================================================
// Kernel B: one LSTM step — all-SMEM operands, f32x2 FMA, split-K=4.
//   128 CTAs x 256 thr. CTA cb owns cols [cb*8, cb*8+8) of each gate.
//   Thread (kg=tid>>6, rg=(tid&63)>>3, bg=tid&7):
//     rows  lr = rg + 8i  (i = gate 0..3, col = rg)  -> V_s row stride 264
//     batch b  = bg + 8j  (j = 0..3)                 -> h_s row stride 1028
//   V slice (32 rows x 1024) restaged in 4 rounds of [32][4 kg][64 k] panels.
//   Inner iter: 4 LDS.128(V) + 4 LDS.128(h) + 32 FFMA2 (pairs over k).
// ============================================================================
#define HPAD  1028
#define VST   264                      // 4 kg * 64 + 8 pad
#define SM_H_FLOATS   (BB * HPAD)      // 32896
#define SM_V_FLOATS   (32 * VST)       // 8448
#define SM_P_FLOATS   (4 * 32 * 36)    // 4608
#define STEP_SMEM ((SM_H_FLOATS + SM_V_FLOATS + SM_P_FLOATS) * 4)  // 183808 B

__global__ void __launch_bounds__(256) lstm_step_kernel(
    const float* __restrict__ Xg,     // [B][4096] for this step
    const float* __restrict__ h_prev, // [B][1024]
    const float* __restrict__ c_prev, // [B][1024]
    const float* __restrict__ V,      // [4096][1024]
    float* __restrict__ h_out1,
    float* __restrict__ h_out2,
    float* __restrict__ c_out)
{
    extern __shared__ float sm[];
    float* h_s = sm;                              // [32][1028]
    float* V_s = sm + SM_H_FLOATS;                // [32][264] = [32][4*64 + pad]
    float* pb  = sm + SM_H_FLOATS + SM_V_FLOATS;  // [4][32][36]

    const int tid = threadIdx.x;
    const int cb  = blockIdx.x;

    // ---- stage h_prev (128 KB), coalesced float4 ----
    #pragma unroll
    for (int idx = tid; idx < BB * (HH / 4); idx += 256) {
        const int b  = idx >> 8;
        const int k4 = idx & 255;
        float4 v = ((const float4*)h_prev)[idx];
        *(float4*)&h_s[b * HPAD + k4 * 4] = v;
    }

    const int kg = tid >> 6;        // 0..3  k-chunk of 256
    const int t  = tid & 63;
    const int rg = t >> 3;          // 0..7  column within the 8 owned cols
    const int bg = t & 7;           // 0..7  batch group

    ull acc2[4][4];
    #pragma unroll
    for (int i = 0; i < 4; i++)
        #pragma unroll
        for (int j = 0; j < 4; j++) acc2[i][j] = 0ULL;

    // smem base offsets for this thread
    const float* vbase = V_s + rg * VST + kg * 64;           // +8i*VST for gate i
    const float* hbase = h_s + bg * HPAD + kg * 256;         // +8j*HPAD, +rnd*64

    for (int rnd = 0; rnd < 4; rnd++) {
        __syncthreads();   // protect V_s from previous round's readers

        // ---- stage V panel: [32 rows][4 kg][64 k], coalesced 256B runs ----
        #pragma unroll
        for (int idx = tid; idx < 2048; idx += 256) {
            const int row = idx >> 6;          // 0..31
            const int rem = idx & 63;
            const int pkg = rem >> 4;          // 0..3
            const int q   = rem & 15;          // 0..15 float4 within 64k
            const int gate = row >> 3;
            const int col  = row & 7;
            const float4 v = *(const float4*)(
                V + ((size_t)gate * HH + cb * 8 + col) * HH
                  + pkg * 256 + rnd * 64 + q * 4);
            *(float4*)&V_s[row * VST + pkg * 64 + q * 4] = v;
        }
        __syncthreads();

        // ---- compute 16 iters of 4k ----
        const float* hb = hbase + rnd * 64;
        #pragma unroll 4
        for (int kk = 0; kk < 64; kk += 4) {
            ulonglong2 hv[4], vv[4];
            #pragma unroll
            for (int j = 0; j < 4; j++)
                hv[j] = *(const ulonglong2*)(hb + j * (8 * HPAD) + kk);
            #pragma unroll
            for (int i = 0; i < 4; i++)
                vv[i] = *(const ulonglong2*)(vbase + i * (8 * VST) + kk);
            #pragma unroll
            for (int i = 0; i < 4; i++)
                #pragma unroll
                for (int j = 0; j < 4; j++) {
                    FFMA2(acc2[i][j], vv[i].x, hv[j].x);
                    FFMA2(acc2[i][j], vv[i].y, hv[j].y);
                }
        }
    }

    // ---- split-K partials -> smem ----
    #pragma unroll
    for (int i = 0; i < 4; i++)
        #pragma unroll
        for (int j = 0; j < 4; j++) {
            float2 f = *(float2*)&acc2[i][j];
            pb[(kg * 32 + (rg + 8 * i)) * 36 + (bg + 8 * j)] = f.x + f.y;
        }
    __syncthreads();

    // ---- combine + elementwise LSTM cell ----
    const int c = tid >> 5;     // 0..7 column
    const int b = tid & 31;     // 0..31 batch

    float gv4[4];
    #pragma unroll
    for (int g = 0; g < 4; g++) {
        const int lr = g * 8 + c;
        float s = pb[(0 * 32 + lr) * 36 + b] + pb[(1 * 32 + lr) * 36 + b]
                + pb[(2 * 32 + lr) * 36 + b] + pb[(3 * 32 + lr) * 36 + b];
        s += __ldg(&Xg[(size_t)b * G4H + (size_t)g * HH + cb * 8 + c]);
        gv4[g] = s;
    }

    const float iv = 1.f / (1.f + __expf(-gv4[0]));
    const float fv = 1.f / (1.f + __expf(-gv4[1]));
    const float gg = tanhf(gv4[2]);
    const float ov = 1.f / (1.f + __expf(-gv4[3]));

    const int col = cb * 8 + c;
    const float cp = c_prev[(size_t)b * HH + col];
    const float cn = fv * cp + iv * gg;
    const float hn = ov * tanhf(cn);

    h_out1[(size_t)b * HH + col] = hn;
    h_out2[(size_t)b * HH + col] = hn;
    c_out[(size_t)b * HH + col]  = cn;
}

// final state copy: h_f = all_h[S-1], c_f = all_c[S-1]
__global__ void copy_final_kernel(const float* __restrict__ h_last,
                                  const float* __restrict__ c_last,
                                  float* __restrict__ h_f,
                                  float* __restrict__ c_f)
{
    int i = blockIdx.x * blockDim.x + threadIdx.x;
    if (i < BH) {
        h_f[i] = h_last[i];
        c_f[i] = c_last[i];
    }
}

// ============================================================================
// Launch
// ============================================================================
extern "C" void kernel_launch(void* const* d_in, const int* in_sizes, int n_in,
                              void* d_out, int out_size)
{
    const float* layer_input = (const float*)d_in[0];  // [S,B,D]
    const float* h_t         = (const float*)d_in[1];  // [B,H]
    const float* c_t         = (const float*)d_in[2];  // [B,H]
    const float* U           = (const float*)d_in[3];  // [4H,D]
    const float* V           = (const float*)d_in[4];  // [4H,H]
    const float* bih         = (const float*)d_in[5];  // [4H]
    const float* bhh         = (const float*)d_in[6];  // [4H]

    float* out = (float*)d_out;
    // output tuple: (all_h, h_f, c_f, all_h, all_c)
    float* all_h1 = out;
    float* h_f    = out + (size_t)SS * BH;
    float* c_f    = h_f + BH;
    float* all_h2 = c_f + BH;
    float* all_c  = all_h2 + (size_t)SS * BH;

    float* Xp = nullptr;
    cudaGetSymbolAddress((void**)&Xp, g_X);

    cudaFuncSetAttribute(lstm_step_kernel,
                         cudaFuncAttributeMaxDynamicSharedMemorySize, STEP_SMEM);

    // Kernel A: input projection + bias
    dim3 gg(G4H / 128, (SS * BB) / 128);   // (32, 128)
    gemm_x_kernel<<<gg, 256>>>(layer_input, U, bih, bhh, Xp);

    // Kernel B: 512 sequential steps (stream-ordered)
    for (int s = 0; s < SS; s++) {
        const float* hp = (s == 0) ? h_t : all_h1 + (size_t)(s - 1) * BH;
        const float* cp = (s == 0) ? c_t : all_c  + (size_t)(s - 1) * BH;
        lstm_step_kernel<<<128, 256, STEP_SMEM>>>(
            Xp + (size_t)s * BB * G4H, hp, cp, V,
            all_h1 + (size_t)s * BH,
            all_h2 + (size_t)s * BH,
            all_c  + (size_t)s * BH);
    }

    copy_final_kernel<<<(BH + 255) / 256, 256>>>(
        all_h1 + (size_t)(SS - 1) * BH,
        all_c  + (size_t)(SS - 1) * BH,
        h_f, c_f);
}

// round 5
// speedup vs baseline: 2.3922x; 1.0113x over previous
#include <cuda_runtime.h>
#include <cuda_bf16.h>
#include <math.h>

// Problem constants
#define SS   512
#define BB   32
#define DD   1024
#define HH   1024
#define G4H  4096          // 4*H
#define BH   (BB*HH)       // 32768
#define GRID 128

typedef unsigned long long ull;

// packed fp32x2 FMA (Blackwell): d.xy += a.xy * b.xy
#define FFMA2(d, a, b) asm("fma.rn.f32x2 %0, %1, %2, %0;" : "+l"(d) : "l"(a), "l"(b))

// ---------------- scratch: X = layer_input @ U^T + bias  [S*B, 4H] ----------
__device__ float g_X[(size_t)SS * BB * G4H];   // 256 MB

// ---------------- global barrier state (returns to 0 after every run) ------
__device__ unsigned g_bar_ctr = 0;
__device__ volatile unsigned g_bar_flag = 0;

// ============================================================================
// Kernel A: SGEMM (NT): X[m][n] = sum_k A[m][k] * W[n][k] + bih[n] + bhh[n]
//   (proven R2/R4 version, plain fp32)
// ============================================================================
__global__ void __launch_bounds__(256) gemm_x_kernel(
    const float* __restrict__ A,
    const float* __restrict__ W,
    const float* __restrict__ bih,
    const float* __restrict__ bhh,
    float* __restrict__ X)
{
    __shared__ float As[16][128];
    __shared__ float Bs[16][128];

    const int bm = blockIdx.y * 128;
    const int bn = blockIdx.x * 128;
    const int tid = threadIdx.x;
    const int tx = tid & 15;
    const int ty = tid >> 4;

    const int lr = tid >> 2;
    const int lc = (tid & 3) * 4;

    const float* Aptr = A + (size_t)(bm + lr) * DD + lc;
    const float* Wptr = W + (size_t)(bn + lr) * DD + lc;

    float acc[8][8];
    #pragma unroll
    for (int i = 0; i < 8; i++)
        #pragma unroll
        for (int j = 0; j < 8; j++) acc[i][j] = 0.f;

    for (int k0 = 0; k0 < DD; k0 += 16) {
        float4 a0 = *(const float4*)(Aptr + k0);
        float4 a1 = *(const float4*)(Aptr + (size_t)64 * DD + k0);
        float4 w0 = *(const float4*)(Wptr + k0);
        float4 w1 = *(const float4*)(Wptr + (size_t)64 * DD + k0);

        __syncthreads();
        As[lc+0][lr]    = a0.x; As[lc+1][lr]    = a0.y; As[lc+2][lr]    = a0.z; As[lc+3][lr]    = a0.w;
        As[lc+0][lr+64] = a1.x; As[lc+1][lr+64] = a1.y; As[lc+2][lr+64] = a1.z; As[lc+3][lr+64] = a1.w;
        Bs[lc+0][lr]    = w0.x; Bs[lc+1][lr]    = w0.y; Bs[lc+2][lr]    = w0.z; Bs[lc+3][lr]    = w0.w;
        Bs[lc+0][lr+64] = w1.x; Bs[lc+1][lr+64] = w1.y; Bs[lc+2][lr+64] = w1.z; Bs[lc+3][lr+64] = w1.w;
        __syncthreads();

        #pragma unroll
        for (int kk = 0; kk < 16; kk++) {
            float ar[8], br[8];
            *(float4*)&ar[0] = *(const float4*)&As[kk][ty * 4];
            *(float4*)&ar[4] = *(const float4*)&As[kk][ty * 4 + 64];
            *(float4*)&br[0] = *(const float4*)&Bs[kk][tx * 4];
            *(float4*)&br[4] = *(const float4*)&Bs[kk][tx * 4 + 64];
            #pragma unroll
            for (int i = 0; i < 8; i++)
                #pragma unroll
                for (int j = 0; j < 8; j++)
                    acc[i][j] += ar[i] * br[j];
        }
    }

    const int gn0 = bn + tx * 4;
    float b0[4], b1[4];
    #pragma unroll
    for (int j = 0; j < 4; j++) {
        b0[j] = bih[gn0 + j]      + bhh[gn0 + j];
        b1[j] = bih[gn0 + 64 + j] + bhh[gn0 + 64 + j];
    }

    #pragma unroll
    for (int ii = 0; ii < 8; ii++) {
        int m = bm + ty * 4 + ((ii < 4) ? ii : (60 + ii));
        float4 o0, o1;
        o0.x = acc[ii][0] + b0[0]; o0.y = acc[ii][1] + b0[1];
        o0.z = acc[ii][2] + b0[2]; o0.w = acc[ii][3] + b0[3];
        o1.x = acc[ii][4] + b1[0]; o1.y = acc[ii][5] + b1[1];
        o1.z = acc[ii][6] + b1[2]; o1.w = acc[ii][7] + b1[3];
        *(float4*)&X[(size_t)m * G4H + gn0]      = o0;
        *(float4*)&X[(size_t)m * G4H + gn0 + 64] = o1;
    }
}

// ============================================================================
// Kernel B: PERSISTENT LSTM — all 512 steps in one launch.
//   128 CTAs x 256 thr, 1 CTA/SM, all co-resident (grid spin barrier).
//   CTA cb owns gate rows {g*1024 + cb*8 + c : g in 0..3, c in 0..7}.
//   V slice (32 rows x 1024 fp32) lives in REGISTERS: thread (kg=tid>>5,
//   lr=tid&31) holds V[row(lr)][kg*128 .. kg*128+128) as 64 f32x2 pairs.
//   Per step: memcpy h -> smem; per batch-pair 32 LDS.128(bcast) + 128 FFMA2;
//   split-K=8 partials -> smem; combine + cell (c in regs); global barrier.
// ============================================================================
#define SM_H   (BB * HH)            // 32768 floats
#define SM_PB  (8 * 32 * 33)        // 8448 floats
#define SM_XG  (4 * 32 * 8)         // 1024 floats
#define PERS_SMEM ((SM_H + SM_PB + SM_XG) * 4)   // 168960 B

__device__ __forceinline__ float fsig(float x) {
    return __fdividef(1.f, 1.f + __expf(-x));
}
__device__ __forceinline__ float ftanh(float x) {
    float e = __expf(-2.f * x);
    return __fdividef(1.f - e, 1.f + e);
}

__global__ void __launch_bounds__(256, 1) lstm_persistent(
    const float* __restrict__ X,      // [S][B][4096] (g_X)
    const float* __restrict__ h0,     // [B][1024]
    const float* __restrict__ c0,     // [B][1024]
    const float* __restrict__ V,      // [4096][1024]
    float* __restrict__ all_h1,
    float* __restrict__ all_h2,
    float* __restrict__ all_c,
    float* __restrict__ h_f,
    float* __restrict__ c_f)
{
    extern __shared__ float sm[];
    float* h_s  = sm;                 // [32][1024]
    float* pb   = sm + SM_H;          // [8][32][33]
    float* xg_s = pb + SM_PB;         // [4][32][8]

    const int tid = threadIdx.x;
    const int cb  = blockIdx.x;

    // ---- compute-phase mapping ----
    const int kg = tid >> 5;          // 0..7 warp = k-slice of 128
    const int lr = tid & 31;          // local row: gate = lr>>3, col = lr&7
    const int gate = lr >> 3;
    const int col8 = lr & 7;

    // ---- combine-phase mapping ----
    const int cbb = tid >> 3;         // batch 0..31
    const int ccc = tid & 7;          // column 0..7
    const int ooff = cbb * HH + cb * 8 + ccc;

    // ---- load V slice into registers (once) ----
    ull vreg[64];
    {
        const ulonglong2* vp = (const ulonglong2*)(
            V + ((size_t)gate * HH + cb * 8 + col8) * HH + kg * 128);
        #pragma unroll
        for (int q = 0; q < 32; q++) {
            ulonglong2 u = vp[q];
            vreg[2 * q]     = u.x;
            vreg[2 * q + 1] = u.y;
        }
    }

    // ---- cell state in register ----
    float c_reg = c0[ooff];

    for (int s = 0; s < SS; s++) {
        // ---- stage h_prev (straight 128KB copy) + Xg tile ----
        const float* hp = (s == 0) ? h0 : (all_h1 + (size_t)(s - 1) * BH);
        #pragma unroll
        for (int idx = tid; idx < BB * HH / 4; idx += 256)
            ((float4*)h_s)[idx] = ((const float4*)hp)[idx];
        {
            const int g    = tid & 3;
            const int half = (tid >> 2) & 1;
            const int b    = tid >> 3;
            float4 xv = *(const float4*)(X + (size_t)s * BB * G4H
                          + (size_t)b * G4H + (size_t)g * HH + cb * 8 + half * 4);
            *(float4*)&xg_s[(g * 32 + b) * 8 + half * 4] = xv;
        }
        __syncthreads();

        // ---- compute: per batch-pair, V(regs) x h(smem broadcast) ----
        const float* hb = h_s + kg * 128;
        for (int b2 = 0; b2 < 32; b2 += 2) {
            ull a0[4] = {0ULL, 0ULL, 0ULL, 0ULL};
            ull a1[4] = {0ULL, 0ULL, 0ULL, 0ULL};
            const ull* p0 = (const ull*)(hb + b2 * HH);
            const ull* p1 = (const ull*)(hb + b2 * HH + HH);
            #pragma unroll
            for (int q = 0; q < 64; q += 4) {
                ulonglong2 u0 = *(const ulonglong2*)&p0[q];
                ulonglong2 u1 = *(const ulonglong2*)&p0[q + 2];
                ulonglong2 w0 = *(const ulonglong2*)&p1[q];
                ulonglong2 w1 = *(const ulonglong2*)&p1[q + 2];
                FFMA2(a0[0], vreg[q],     u0.x);
                FFMA2(a0[1], vreg[q + 1], u0.y);
                FFMA2(a0[2], vreg[q + 2], u1.x);
                FFMA2(a0[3], vreg[q + 3], u1.y);
                FFMA2(a1[0], vreg[q],     w0.x);
                FFMA2(a1[1], vreg[q + 1], w0.y);
                FFMA2(a1[2], vreg[q + 2], w1.x);
                FFMA2(a1[3], vreg[q + 3], w1.y);
            }
            float2 f00 = *(float2*)&a0[0], f01 = *(float2*)&a0[1];
            float2 f02 = *(float2*)&a0[2], f03 = *(float2*)&a0[3];
            float2 f10 = *(float2*)&a1[0], f11 = *(float2*)&a1[1];
            float2 f12 = *(float2*)&a1[2], f13 = *(float2*)&a1[3];
            pb[(kg * 32 + lr) * 33 + b2] =
                (f00.x + f00.y) + (f01.x + f01.y) + (f02.x + f02.y) + (f03.x + f03.y);
            pb[(kg * 32 + lr) * 33 + b2 + 1] =
                (f10.x + f10.y) + (f11.x + f11.y) + (f12.x + f12.y) + (f13.x + f13.y);
        }
        __syncthreads();

        // ---- combine + cell ----
        float g4[4];
        #pragma unroll
        for (int g = 0; g < 4; g++) {
            const int lrr = g * 8 + ccc;
            float acc = xg_s[(g * 32 + cbb) * 8 + ccc];
            #pragma unroll
            for (int k2 = 0; k2 < 8; k2++)
                acc += pb[(k2 * 32 + lrr) * 33 + cbb];
            g4[g] = acc;
        }

        const float iv = fsig(g4[0]);
        const float fv = fsig(g4[1]);
        const float gg = ftanh(g4[2]);
        const float ov = fsig(g4[3]);

        c_reg = fv * c_reg + iv * gg;
        const float hn = ov * ftanh(c_reg);

        all_h1[(size_t)s * BH + ooff] = hn;
        all_h2[(size_t)s * BH + ooff] = hn;
        all_c [(size_t)s * BH + ooff] = c_reg;
        if (s == SS - 1) {
            h_f[ooff] = hn;
            c_f[ooff] = c_reg;
        }

        // ---- grid barrier (sense-reversing; state returns to 0 each run) ----
        __threadfence();
        __syncthreads();
        if (tid == 0) {
            const unsigned target = (s & 1) ? 0u : 1u;
            unsigned old = atomicAdd(&g_bar_ctr, 1u);
            if (old == GRID - 1) {
                atomicExch(&g_bar_ctr, 0u);
                __threadfence();
                g_bar_flag = target;
            } else {
                while (g_bar_flag != target) { }
            }
            __threadfence();
        }
        __syncthreads();
    }
}

// ============================================================================
// Launch
// ============================================================================
extern "C" void kernel_launch(void* const* d_in, const int* in_sizes, int n_in,
                              void* d_out, int out_size)
{
    const float* layer_input = (const float*)d_in[0];  // [S,B,D]
    const float* h_t         = (const float*)d_in[1];  // [B,H]
    const float* c_t         = (const float*)d_in[2];  // [B,H]
    const float* U           = (const float*)d_in[3];  // [4H,D]
    const float* V           = (const float*)d_in[4];  // [4H,H]
    const float* bih         = (const float*)d_in[5];  // [4H]
    const float* bhh         = (const float*)d_in[6];  // [4H]

    float* out = (float*)d_out;
    // output tuple: (all_h, h_f, c_f, all_h, all_c)
    float* all_h1 = out;
    float* h_f    = out + (size_t)SS * BH;
    float* c_f    = h_f + BH;
    float* all_h2 = c_f + BH;
    float* all_c  = all_h2 + (size_t)SS * BH;

    float* Xp = nullptr;
    cudaGetSymbolAddress((void**)&Xp, g_X);

    cudaFuncSetAttribute(lstm_persistent,
                         cudaFuncAttributeMaxDynamicSharedMemorySize, PERS_SMEM);

    // Kernel A: input projection + bias
    dim3 gg(G4H / 128, (SS * BB) / 128);   // (32, 128)
    gemm_x_kernel<<<gg, 256>>>(layer_input, U, bih, bhh, Xp);

    // Kernel B: persistent recurrence (all 512 steps)
    lstm_persistent<<<GRID, 256, PERS_SMEM>>>(
        Xp, h_t, c_t, V, all_h1, all_h2, all_c, h_f, c_f);
}

// round 7
// speedup vs baseline: 2.8083x; 1.1739x over previous
#include <cuda_runtime.h>
#include <cuda_bf16.h>
#include <math.h>

// Problem constants
#define SS   512
#define BB   32
#define DD   1024
#define HH   1024
#define G4H  4096          // 4*H
#define BH   (BB*HH)       // 32768
#define GRID 128

typedef unsigned long long ull;

// packed fp32x2 FMA (Blackwell): d.xy += a.xy * b.xy
#define FFMA2(d, a, b) asm("fma.rn.f32x2 %0, %1, %2, %0;" : "+l"(d) : "l"(a), "l"(b))
// pack {s, s} into a 64-bit f32x2
#define PACK2(d, s) asm("mov.b64 %0, {%1, %1};" : "=l"(d) : "r"(s))

// ---------------- scratch: X = layer_input @ U^T + bias  [S*B, 4H] ----------
__device__ float g_X[(size_t)SS * BB * G4H];   // 256 MB

// ---------------- global barrier state (returns to 0 after every run) ------
__device__ unsigned g_bar_ctr = 0;
__device__ volatile unsigned g_bar_flag = 0;

// ============================================================================
// Kernel A: SGEMM (NT) with f32x2 packed FMA (pairs over n) — proven in R3.
// ============================================================================
__global__ void __launch_bounds__(256) gemm_x_kernel(
    const float* __restrict__ A,
    const float* __restrict__ W,
    const float* __restrict__ bih,
    const float* __restrict__ bhh,
    float* __restrict__ X)
{
    __shared__ float As[16][128];
    __shared__ float Bs[16][128];

    const int bm = blockIdx.y * 128;
    const int bn = blockIdx.x * 128;
    const int tid = threadIdx.x;
    const int tx = tid & 15;
    const int ty = tid >> 4;

    const int lr = tid >> 2;
    const int lc = (tid & 3) * 4;

    const float* Aptr = A + (size_t)(bm + lr) * DD + lc;
    const float* Wptr = W + (size_t)(bn + lr) * DD + lc;

    ull acc2[8][4];
    #pragma unroll
    for (int i = 0; i < 8; i++)
        #pragma unroll
        for (int j = 0; j < 4; j++) acc2[i][j] = 0ULL;

    for (int k0 = 0; k0 < DD; k0 += 16) {
        float4 a0 = *(const float4*)(Aptr + k0);
        float4 a1 = *(const float4*)(Aptr + (size_t)64 * DD + k0);
        float4 w0 = *(const float4*)(Wptr + k0);
        float4 w1 = *(const float4*)(Wptr + (size_t)64 * DD + k0);

        __syncthreads();
        As[lc+0][lr]    = a0.x; As[lc+1][lr]    = a0.y; As[lc+2][lr]    = a0.z; As[lc+3][lr]    = a0.w;
        As[lc+0][lr+64] = a1.x; As[lc+1][lr+64] = a1.y; As[lc+2][lr+64] = a1.z; As[lc+3][lr+64] = a1.w;
        Bs[lc+0][lr]    = w0.x; Bs[lc+1][lr]    = w0.y; Bs[lc+2][lr]    = w0.z; Bs[lc+3][lr]    = w0.w;
        Bs[lc+0][lr+64] = w1.x; Bs[lc+1][lr+64] = w1.y; Bs[lc+2][lr+64] = w1.z; Bs[lc+3][lr+64] = w1.w;
        __syncthreads();

        #pragma unroll
        for (int kk = 0; kk < 16; kk++) {
            float ar[8];
            *(float4*)&ar[0] = *(const float4*)&As[kk][ty * 4];
            *(float4*)&ar[4] = *(const float4*)&As[kk][ty * 4 + 64];
            ulonglong2 b0 = *(const ulonglong2*)&Bs[kk][tx * 4];
            ulonglong2 b1 = *(const ulonglong2*)&Bs[kk][tx * 4 + 64];
            ull br2[4] = {b0.x, b0.y, b1.x, b1.y};
            ull ap[8];
            #pragma unroll
            for (int i = 0; i < 8; i++) PACK2(ap[i], __float_as_uint(ar[i]));
            #pragma unroll
            for (int i = 0; i < 8; i++)
                #pragma unroll
                for (int j = 0; j < 4; j++)
                    FFMA2(acc2[i][j], ap[i], br2[j]);
        }
    }

    const int gn0 = bn + tx * 4;
    float b0v[4], b1v[4];
    #pragma unroll
    for (int j = 0; j < 4; j++) {
        b0v[j] = bih[gn0 + j]      + bhh[gn0 + j];
        b1v[j] = bih[gn0 + 64 + j] + bhh[gn0 + 64 + j];
    }

    #pragma unroll
    for (int ii = 0; ii < 8; ii++) {
        int m = bm + ty * 4 + ((ii < 4) ? ii : (60 + ii));
        float2 f0 = *(float2*)&acc2[ii][0];
        float2 f1 = *(float2*)&acc2[ii][1];
        float2 f2 = *(float2*)&acc2[ii][2];
        float2 f3 = *(float2*)&acc2[ii][3];
        float4 o0, o1;
        o0.x = f0.x + b0v[0]; o0.y = f0.y + b0v[1];
        o0.z = f1.x + b0v[2]; o0.w = f1.y + b0v[3];
        o1.x = f2.x + b1v[0]; o1.y = f2.y + b1v[1];
        o1.z = f3.x + b1v[2]; o1.w = f3.y + b1v[3];
        *(float4*)&X[(size_t)m * G4H + gn0]      = o0;
        *(float4*)&X[(size_t)m * G4H + gn0 + 64] = o1;
    }
}

// ============================================================================
// Kernel B: PERSISTENT LSTM — all 512 steps, one launch.
//   128 CTAs x 256 thr. CTA cb owns 32 gate rows {g*1024 + cb*8 + c}.
//   Thread tile: 2 rows x 64 k in REGISTERS (ks = tid>>4 k-slice of 64,
//   rp = tid&15 row pair). Each h read feeds 2 rows -> LDS:FFMA2 = 1:4.
//   h_s k-slice stride 2180 floats (== 4 banks mod 32) so the two half-warp
//   broadcast addresses land in distinct bank quads. Partials folded with
//   shfl_xor(16), then pb[8 warps][32 rows][33] in smem. c stays in a reg.
// ============================================================================
#define KS_STRIDE 2180                       // 32*68 + 4
#define SM_H   (16 * KS_STRIDE)              // 34880 floats
#define SM_PB  (8 * 32 * 33)                 // 8448 floats
#define SM_XG  (4 * 32 * 8)                  // 1024 floats
#define PERS_SMEM ((SM_H + SM_PB + SM_XG) * 4)   // 177408 B

__device__ __forceinline__ float fsig(float x) {
    return __fdividef(1.f, 1.f + __expf(-x));
}
__device__ __forceinline__ float ftanh(float x) {
    float e = __expf(-2.f * x);
    return __fdividef(1.f - e, 1.f + e);
}

__global__ void __launch_bounds__(256, 1) lstm_persistent(
    const float* __restrict__ X,      // [S][B][4096] (g_X)
    const float* __restrict__ h0,     // [B][1024]
    const float* __restrict__ c0,     // [B][1024]
    const float* __restrict__ V,      // [4096][1024]
    float* __restrict__ all_h1,
    float* __restrict__ all_h2,
    float* __restrict__ all_c,
    float* __restrict__ h_f,
    float* __restrict__ c_f)
{
    extern __shared__ float sm[];
    float* h_s  = sm;                 // [16 ks][32 b][68] (+4 skew per ks)
    float* pb   = sm + SM_H;          // [8][32][33]
    float* xg_s = pb + SM_PB;         // [4][32][8]

    const int tid  = threadIdx.x;
    const int cb   = blockIdx.x;
    const int lane = tid & 31;
    const int w    = tid >> 5;        // warp 0..7

    // ---- compute-phase tile ----
    const int ks = tid >> 4;          // 0..15  k-slice of 64
    const int rp = tid & 15;          // row pair: local rows 2rp, 2rp+1

    // ---- combine-phase mapping ----
    const int cbb = tid >> 3;         // batch 0..31
    const int ccc = tid & 7;          // column 0..7
    const int ooff = cbb * HH + cb * 8 + ccc;

    // ---- load V tile into registers (once): 2 rows x 64 k = 32 ull each ----
    ull vreg[2][32];
    #pragma unroll
    for (int r = 0; r < 2; r++) {
        const int lrow = 2 * rp + r;
        const size_t grow = (size_t)(lrow >> 3) * HH + cb * 8 + (lrow & 7);
        const ulonglong2* vp = (const ulonglong2*)(V + grow * HH + ks * 64);
        #pragma unroll
        for (int q = 0; q < 16; q++) {
            ulonglong2 u = vp[q];
            vreg[r][2 * q]     = u.x;
            vreg[r][2 * q + 1] = u.y;
        }
    }

    float c_reg = c0[ooff];

    const float* hbase = h_s + ks * KS_STRIDE;

    for (int s = 0; s < SS; s++) {
        // ---- stage h_prev into skewed smem ----
        const float* hp = (s == 0) ? h0 : (all_h1 + (size_t)(s - 1) * BH);
        #pragma unroll
        for (int idx = tid; idx < BB * HH / 4; idx += 256) {
            const int b   = idx >> 8;       // batch
            const int k4  = idx & 255;      // float4 index in row
            const int k   = k4 * 4;
            const int ksi = k >> 6;
            const int kk  = k & 63;
            float4 v = ((const float4*)hp)[idx];
            *(float4*)&h_s[ksi * KS_STRIDE + b * 68 + kk] = v;
        }
        {   // Xg tile for this CTA: [4][32][8]
            const int g    = tid & 3;
            const int half = (tid >> 2) & 1;
            const int b    = tid >> 3;
            float4 xv = *(const float4*)(X + (size_t)s * BB * G4H
                          + (size_t)b * G4H + (size_t)g * HH + cb * 8 + half * 4);
            *(float4*)&xg_s[(g * 32 + b) * 8 + half * 4] = xv;
        }
        __syncthreads();

        // ---- compute: batch pairs, V in regs, h broadcast from smem ----
        for (int b2 = 0; b2 < 32; b2 += 2) {
            const ulonglong2* hp0 = (const ulonglong2*)(hbase + b2 * 68);
            const ulonglong2* hp1 = (const ulonglong2*)(hbase + b2 * 68 + 68);
            ull a00 = 0ULL, a01 = 0ULL, a10 = 0ULL, a11 = 0ULL;
            #pragma unroll
            for (int q = 0; q < 16; q++) {          // FULL 64-k slice
                ulonglong2 hx = hp0[q];
                ulonglong2 hy = hp1[q];
                FFMA2(a00, vreg[0][2 * q],     hx.x);
                FFMA2(a10, vreg[1][2 * q],     hx.x);
                FFMA2(a01, vreg[0][2 * q],     hy.x);
                FFMA2(a11, vreg[1][2 * q],     hy.x);
                FFMA2(a00, vreg[0][2 * q + 1], hx.y);
                FFMA2(a10, vreg[1][2 * q + 1], hx.y);
                FFMA2(a01, vreg[0][2 * q + 1], hy.y);
                FFMA2(a11, vreg[1][2 * q + 1], hy.y);
            }
            float2 f;
            f = *(float2*)&a00; float s00 = f.x + f.y;
            f = *(float2*)&a10; float s10 = f.x + f.y;
            f = *(float2*)&a01; float s01 = f.x + f.y;
            f = *(float2*)&a11; float s11 = f.x + f.y;

            // fold the two k-slices of this warp (lanes l and l^16 share rp)
            s00 += __shfl_xor_sync(0xffffffffu, s00, 16);
            s10 += __shfl_xor_sync(0xffffffffu, s10, 16);
            s01 += __shfl_xor_sync(0xffffffffu, s01, 16);
            s11 += __shfl_xor_sync(0xffffffffu, s11, 16);

            if (lane < 16) {
                const int base = (w * 32 + 2 * rp) * 33;
                pb[base + b2]           = s00;
                pb[base + 33 + b2]      = s10;
                pb[base + b2 + 1]       = s01;
                pb[base + 33 + b2 + 1]  = s11;
            }
        }
        __syncthreads();

        // ---- combine + cell ----
        float g4[4];
        #pragma unroll
        for (int g = 0; g < 4; g++) {
            const int lrr = g * 8 + ccc;
            float acc = xg_s[(g * 32 + cbb) * 8 + ccc];
            #pragma unroll
            for (int k2 = 0; k2 < 8; k2++)
                acc += pb[(k2 * 32 + lrr) * 33 + cbb];
            g4[g] = acc;
        }

        const float iv = fsig(g4[0]);
        const float fv = fsig(g4[1]);
        const float gg = ftanh(g4[2]);
        const float ov = fsig(g4[3]);

        c_reg = fv * c_reg + iv * gg;
        const float hn = ov * ftanh(c_reg);

        all_h1[(size_t)s * BH + ooff] = hn;
        all_h2[(size_t)s * BH + ooff] = hn;
        all_c [(size_t)s * BH + ooff] = c_reg;
        if (s == SS - 1) {
            h_f[ooff] = hn;
            c_f[ooff] = c_reg;
        }

        // ---- grid barrier (sense-reversing; returns to 0 each run) ----
        __threadfence();
        __syncthreads();
        if (tid == 0) {
            const unsigned target = (s & 1) ? 0u : 1u;
            unsigned old = atomicAdd(&g_bar_ctr, 1u);
            if (old == GRID - 1) {
                atomicExch(&g_bar_ctr, 0u);
                __threadfence();
                g_bar_flag = target;
            } else {
                while (g_bar_flag != target) { }
            }
            __threadfence();
        }
        __syncthreads();
    }
}

// ============================================================================
// Launch
// ============================================================================
extern "C" void kernel_launch(void* const* d_in, const int* in_sizes, int n_in,
                              void* d_out, int out_size)
{
    const float* layer_input = (const float*)d_in[0];  // [S,B,D]
    const float* h_t         = (const float*)d_in[1];  // [B,H]
    const float* c_t         = (const float*)d_in[2];  // [B,H]
    const float* U           = (const float*)d_in[3];  // [4H,D]
    const float* V           = (const float*)d_in[4];  // [4H,H]
    const float* bih         = (const float*)d_in[5];  // [4H]
    const float* bhh         = (const float*)d_in[6];  // [4H]

    float* out = (float*)d_out;
    // output tuple: (all_h, h_f, c_f, all_h, all_c)
    float* all_h1 = out;
    float* h_f    = out + (size_t)SS * BH;
    float* c_f    = h_f + BH;
    float* all_h2 = c_f + BH;
    float* all_c  = all_h2 + (size_t)SS * BH;

    float* Xp = nullptr;
    cudaGetSymbolAddress((void**)&Xp, g_X);

    cudaFuncSetAttribute(lstm_persistent,
                         cudaFuncAttributeMaxDynamicSharedMemorySize, PERS_SMEM);

    // Kernel A: input projection + bias
    dim3 gg(G4H / 128, (SS * BB) / 128);   // (32, 128)
    gemm_x_kernel<<<gg, 256>>>(layer_input, U, bih, bhh, Xp);

    // Kernel B: persistent recurrence (all 512 steps)
    lstm_persistent<<<GRID, 256, PERS_SMEM>>>(
        Xp, h_t, c_t, V, all_h1, all_h2, all_c, h_f, c_f);
}

// round 9
// speedup vs baseline: 2.9746x; 1.0592x over previous
#include <cuda_runtime.h>
#include <cuda_bf16.h>
#include <math.h>
#include <stdint.h>

// Problem constants
#define SS   512
#define BB   32
#define DD   1024
#define HH   1024
#define G4H  4096          // 4*H
#define BH   (BB*HH)       // 32768
#define GRID 128

typedef unsigned long long ull;

// packed fp32x2 FMA (Blackwell): d.xy += a.xy * b.xy
#define FFMA2(d, a, b) asm("fma.rn.f32x2 %0, %1, %2, %0;" : "+l"(d) : "l"(a), "l"(b))

// ldmatrix x4 (non-transposed, b16)
#define LDSM_X4(r0, r1, r2, r3, addr) \
    asm volatile("ldmatrix.sync.aligned.m8n8.x4.shared.b16 {%0,%1,%2,%3}, [%4];" \
                 : "=r"(r0), "=r"(r1), "=r"(r2), "=r"(r3) : "r"(addr))

// HMMA m16n8k16 bf16 -> f32
#define MMA16816(d, a, b) \
    asm volatile("mma.sync.aligned.m16n8k16.row.col.f32.bf16.bf16.f32 " \
                 "{%0,%1,%2,%3}, {%4,%5,%6,%7}, {%8,%9}, {%0,%1,%2,%3};" \
                 : "+f"((d)[0]), "+f"((d)[1]), "+f"((d)[2]), "+f"((d)[3]) \
                 : "r"((a)[0]), "r"((a)[1]), "r"((a)[2]), "r"((a)[3]), \
                   "r"((b)[0]), "r"((b)[1]))

// ---------------- scratch ---------------------------------------------------
__device__ float g_X[(size_t)SS * BB * G4H];             // 256 MB
__device__ __nv_bfloat16 g_Ahi[(size_t)SS * BB * DD];    // 32 MB
__device__ __nv_bfloat16 g_Alo[(size_t)SS * BB * DD];    // 32 MB
__device__ __nv_bfloat16 g_Uhi[(size_t)G4H * DD];        // 8 MB
__device__ __nv_bfloat16 g_Ulo[(size_t)G4H * DD];        // 8 MB

// ---------------- global barrier state (returns to 0 after every run) ------
__device__ unsigned g_bar_ctr = 0;
__device__ volatile unsigned g_bar_flag = 0;

__device__ __forceinline__ uint32_t smem_u32(const void* p) {
    uint32_t a;
    asm("{ .reg .u64 t; cvta.to.shared.u64 t, %1; cvt.u32.u64 %0, t; }"
        : "=r"(a) : "l"(p));
    return a;
}

// ============================================================================
// Split fp32 -> bf16 (hi, lo):  x = hi + lo + O(2^-18 x)
// ============================================================================
__global__ void __launch_bounds__(256) split_bf16(
    const float* __restrict__ src,
    __nv_bfloat16* __restrict__ hi,
    __nv_bfloat16* __restrict__ lo,
    int n4)
{
    int i = blockIdx.x * 256 + threadIdx.x;
    if (i >= n4) return;
    float4 v = ((const float4*)src)[i];
    float vv[4] = {v.x, v.y, v.z, v.w};
    unsigned short hs[4], ls[4];
    #pragma unroll
    for (int j = 0; j < 4; j++) {
        __nv_bfloat16 h = __float2bfloat16(vv[j]);
        __nv_bfloat16 l = __float2bfloat16(vv[j] - __bfloat162float(h));
        hs[j] = *reinterpret_cast<unsigned short*>(&h);
        ls[j] = *reinterpret_cast<unsigned short*>(&l);
    }
    uint2 ph, pl;
    ph.x = (uint32_t)hs[0] | ((uint32_t)hs[1] << 16);
    ph.y = (uint32_t)hs[2] | ((uint32_t)hs[3] << 16);
    pl.x = (uint32_t)ls[0] | ((uint32_t)ls[1] << 16);
    pl.y = (uint32_t)ls[2] | ((uint32_t)ls[3] << 16);
    ((uint2*)hi)[i] = ph;
    ((uint2*)lo)[i] = pl;
}

// ============================================================================
// Kernel A: HMMA (mma.sync m16n8k16 bf16) GEMM
//   X[m][n] = sum_k A[m][k]*U[n][k] + bias[n]
//   hi/lo split: D += Ahi*Bhi + Ahi*Blo + Alo*Bhi  (fp32 accum)
//   128x128 tile, BK=32, 8 warps (4m x 2n), warp tile 32x64 (2m x 8n atoms).
//   smem rows padded to 40 halves (80B) -> conflict-free ldmatrix phases.
// ============================================================================
#define RPAD 40   // halves per smem row (32 data + 8 pad)

__global__ void __launch_bounds__(256) gemm_x_hmma(
    const __nv_bfloat16* __restrict__ Ahi, const __nv_bfloat16* __restrict__ Alo,
    const __nv_bfloat16* __restrict__ Bhi, const __nv_bfloat16* __restrict__ Blo,
    const float* __restrict__ bih, const float* __restrict__ bhh,
    float* __restrict__ X)
{
    __shared__ __align__(16) unsigned short sAhi[128 * RPAD];
    __shared__ __align__(16) unsigned short sAlo[128 * RPAD];
    __shared__ __align__(16) unsigned short sBhi[128 * RPAD];
    __shared__ __align__(16) unsigned short sBlo[128 * RPAD];
    __shared__ float bias_s[128];

    const int tid  = threadIdx.x;
    const int lane = tid & 31;
    const int wid  = tid >> 5;
    const int wm   = (wid >> 1) * 32;   // warp m offset in tile
    const int wn   = (wid & 1) * 64;    // warp n offset in tile

    const int bn = blockIdx.x * 128;
    const int bm = blockIdx.y * 128;

    if (tid < 128) bias_s[tid] = bih[bn + tid] + bhh[bn + tid];

    // staging: 512 16B-segments per tile; this thread owns segs tid*2, tid*2+1
    const int seg0 = tid * 2;
    const int row0s = seg0 >> 2, sk0 = (seg0 & 3) * 8;       // halves offset
    const int row1s = (seg0 + 1) >> 2, sk1 = ((seg0 + 1) & 3) * 8;

    const __nv_bfloat16* gsrc[4] = {
        Ahi + (size_t)bm * DD, Alo + (size_t)bm * DD,
        Bhi + (size_t)bn * DD, Blo + (size_t)bn * DD };
    unsigned short* stile[4] = { sAhi, sAlo, sBhi, sBlo };

    // ldmatrix per-lane byte offsets (within a tile), excluding k-step
    // A frag (m16k16): row = m0 + (lane&15), col = (lane>>4)*8
    const uint32_t aoff = (uint32_t)(lane & 15) * (RPAD * 2) + (uint32_t)(lane >> 4) * 16;
    // B frag pair (2 n-atoms): row = n0 + (lane&7) + (lane>>4)*8, col = ((lane>>3)&1)*8
    const uint32_t boff = ((uint32_t)((lane & 7) + (lane >> 4) * 8)) * (RPAD * 2)
                        + (uint32_t)((lane >> 3) & 1) * 16;

    const uint32_t sbAhi = smem_u32(sAhi), sbAlo = smem_u32(sAlo);
    const uint32_t sbBhi = smem_u32(sBhi), sbBlo = smem_u32(sBlo);

    float acc[2][8][4];
    #pragma unroll
    for (int im = 0; im < 2; im++)
        #pragma unroll
        for (int ia = 0; ia < 8; ia++)
            #pragma unroll
            for (int q = 0; q < 4; q++) acc[im][ia][q] = 0.f;

    for (int kc = 0; kc < 32; kc++) {
        // ---- load this chunk's 16B segments from gmem ----
        uint4 v0[4], v1[4];
        #pragma unroll
        for (int t = 0; t < 4; t++) {
            v0[t] = *(const uint4*)(gsrc[t] + (size_t)row0s * DD + kc * 32 + sk0);
            v1[t] = *(const uint4*)(gsrc[t] + (size_t)row1s * DD + kc * 32 + sk1);
        }
        __syncthreads();   // previous chunk's readers done
        #pragma unroll
        for (int t = 0; t < 4; t++) {
            *(uint4*)&stile[t][row0s * RPAD + sk0] = v0[t];
            *(uint4*)&stile[t][row1s * RPAD + sk1] = v1[t];
        }
        __syncthreads();

        // ---- compute: 2 k-steps of 16 ----
        #pragma unroll
        for (int ks2 = 0; ks2 < 2; ks2++) {
            const uint32_t kb = ks2 * 32;   // 16 halves = 32 bytes

            uint32_t ah[2][4], al[2][4];
            #pragma unroll
            for (int im = 0; im < 2; im++) {
                const uint32_t ro = (uint32_t)(wm + im * 16) * (RPAD * 2) + kb;
                LDSM_X4(ah[im][0], ah[im][1], ah[im][2], ah[im][3], sbAhi + ro + aoff);
                LDSM_X4(al[im][0], al[im][1], al[im][2], al[im][3], sbAlo + ro + aoff);
            }
            uint32_t bh[4][4], bl[4][4];
            #pragma unroll
            for (int g = 0; g < 4; g++) {
                const uint32_t ro = (uint32_t)(wn + g * 16) * (RPAD * 2) + kb;
                LDSM_X4(bh[g][0], bh[g][1], bh[g][2], bh[g][3], sbBhi + ro + boff);
                LDSM_X4(bl[g][0], bl[g][1], bl[g][2], bl[g][3], sbBlo + ro + boff);
            }

            #pragma unroll
            for (int im = 0; im < 2; im++)
                #pragma unroll
                for (int g = 0; g < 4; g++)
                    #pragma unroll
                    for (int h = 0; h < 2; h++) {
                        const int ia = 2 * g + h;
                        uint32_t bhf[2] = { bh[g][h * 2], bh[g][h * 2 + 1] };
                        uint32_t blf[2] = { bl[g][h * 2], bl[g][h * 2 + 1] };
                        MMA16816(acc[im][ia], ah[im], bhf);
                        MMA16816(acc[im][ia], ah[im], blf);
                        MMA16816(acc[im][ia], al[im], bhf);
                    }
        }
    }

    // ---- epilogue: bias + store ----
    const int trow = lane >> 2;
    const int tcol = (lane & 3) * 2;
    #pragma unroll
    for (int im = 0; im < 2; im++) {
        #pragma unroll
        for (int ia = 0; ia < 8; ia++) {
            const int nloc = wn + ia * 8 + tcol;
            const float b0 = bias_s[nloc], b1 = bias_s[nloc + 1];
            const size_t r0 = (size_t)(bm + wm + im * 16 + trow) * G4H + bn + nloc;
            const size_t r1 = r0 + (size_t)8 * G4H;
            float2 o0 = { acc[im][ia][0] + b0, acc[im][ia][1] + b1 };
            float2 o1 = { acc[im][ia][2] + b0, acc[im][ia][3] + b1 };
            *(float2*)&X[r0] = o0;
            *(float2*)&X[r1] = o1;
        }
    }
}

// ============================================================================
// Kernel B: PERSISTENT LSTM (unchanged from R7, proven: rel_err 6.2e-7)
// ============================================================================
#define KS_STRIDE 2180
#define SM_H   (16 * KS_STRIDE)
#define SM_PB  (8 * 32 * 33)
#define SM_XG  (4 * 32 * 8)
#define PERS_SMEM ((SM_H + SM_PB + SM_XG) * 4)

__device__ __forceinline__ float fsig(float x) {
    return __fdividef(1.f, 1.f + __expf(-x));
}
__device__ __forceinline__ float ftanh(float x) {
    float e = __expf(-2.f * x);
    return __fdividef(1.f - e, 1.f + e);
}

__global__ void __launch_bounds__(256, 1) lstm_persistent(
    const float* __restrict__ X,
    const float* __restrict__ h0,
    const float* __restrict__ c0,
    const float* __restrict__ V,
    float* __restrict__ all_h1,
    float* __restrict__ all_h2,
    float* __restrict__ all_c,
    float* __restrict__ h_f,
    float* __restrict__ c_f)
{
    extern __shared__ float sm[];
    float* h_s  = sm;
    float* pb   = sm + SM_H;
    float* xg_s = pb + SM_PB;

    const int tid  = threadIdx.x;
    const int cb   = blockIdx.x;
    const int lane = tid & 31;
    const int w    = tid >> 5;

    const int ks = tid >> 4;
    const int rp = tid & 15;

    const int cbb = tid >> 3;
    const int ccc = tid & 7;
    const int ooff = cbb * HH + cb * 8 + ccc;

    ull vreg[2][32];
    #pragma unroll
    for (int r = 0; r < 2; r++) {
        const int lrow = 2 * rp + r;
        const size_t grow = (size_t)(lrow >> 3) * HH + cb * 8 + (lrow & 7);
        const ulonglong2* vp = (const ulonglong2*)(V + grow * HH + ks * 64);
        #pragma unroll
        for (int q = 0; q < 16; q++) {
            ulonglong2 u = vp[q];
            vreg[r][2 * q]     = u.x;
            vreg[r][2 * q + 1] = u.y;
        }
    }

    float c_reg = c0[ooff];
    const float* hbase = h_s + ks * KS_STRIDE;

    for (int s = 0; s < SS; s++) {
        const float* hp = (s == 0) ? h0 : (all_h1 + (size_t)(s - 1) * BH);
        #pragma unroll
        for (int idx = tid; idx < BB * HH / 4; idx += 256) {
            const int b   = idx >> 8;
            const int k4  = idx & 255;
            const int k   = k4 * 4;
            const int ksi = k >> 6;
            const int kk  = k & 63;
            float4 v = ((const float4*)hp)[idx];
            *(float4*)&h_s[ksi * KS_STRIDE + b * 68 + kk] = v;
        }
        {
            const int g    = tid & 3;
            const int half = (tid >> 2) & 1;
            const int b    = tid >> 3;
            float4 xv = *(const float4*)(X + (size_t)s * BB * G4H
                          + (size_t)b * G4H + (size_t)g * HH + cb * 8 + half * 4);
            *(float4*)&xg_s[(g * 32 + b) * 8 + half * 4] = xv;
        }
        __syncthreads();

        for (int b2 = 0; b2 < 32; b2 += 2) {
            const ulonglong2* hp0 = (const ulonglong2*)(hbase + b2 * 68);
            const ulonglong2* hp1 = (const ulonglong2*)(hbase + b2 * 68 + 68);
            ull a00 = 0ULL, a01 = 0ULL, a10 = 0ULL, a11 = 0ULL;
            #pragma unroll
            for (int q = 0; q < 16; q++) {
                ulonglong2 hx = hp0[q];
                ulonglong2 hy = hp1[q];
                FFMA2(a00, vreg[0][2 * q],     hx.x);
                FFMA2(a10, vreg[1][2 * q],     hx.x);
                FFMA2(a01, vreg[0][2 * q],     hy.x);
                FFMA2(a11, vreg[1][2 * q],     hy.x);
                FFMA2(a00, vreg[0][2 * q + 1], hx.y);
                FFMA2(a10, vreg[1][2 * q + 1], hx.y);
                FFMA2(a01, vreg[0][2 * q + 1], hy.y);
                FFMA2(a11, vreg[1][2 * q + 1], hy.y);
            }
            float2 f;
            f = *(float2*)&a00; float s00 = f.x + f.y;
            f = *(float2*)&a10; float s10 = f.x + f.y;
            f = *(float2*)&a01; float s01 = f.x + f.y;
            f = *(float2*)&a11; float s11 = f.x + f.y;

            s00 += __shfl_xor_sync(0xffffffffu, s00, 16);
            s10 += __shfl_xor_sync(0xffffffffu, s10, 16);
            s01 += __shfl_xor_sync(0xffffffffu, s01, 16);
            s11 += __shfl_xor_sync(0xffffffffu, s11, 16);

            if (lane < 16) {
                const int base = (w * 32 + 2 * rp) * 33;
                pb[base + b2]           = s00;
                pb[base + 33 + b2]      = s10;
                pb[base + b2 + 1]       = s01;
                pb[base + 33 + b2 + 1]  = s11;
            }
        }
        __syncthreads();

        float g4[4];
        #pragma unroll
        for (int g = 0; g < 4; g++) {
            const int lrr = g * 8 + ccc;
            float acc = xg_s[(g * 32 + cbb) * 8 + ccc];
            #pragma unroll
            for (int k2 = 0; k2 < 8; k2++)
                acc += pb[(k2 * 32 + lrr) * 33 + cbb];
            g4[g] = acc;
        }

        const float iv = fsig(g4[0]);
        const float fv = fsig(g4[1]);
        const float gg = ftanh(g4[2]);
        const float ov = fsig(g4[3]);

        c_reg = fv * c_reg + iv * gg;
        const float hn = ov * ftanh(c_reg);

        all_h1[(size_t)s * BH + ooff] = hn;
        all_h2[(size_t)s * BH + ooff] = hn;
        all_c [(size_t)s * BH + ooff] = c_reg;
        if (s == SS - 1) {
            h_f[ooff] = hn;
            c_f[ooff] = c_reg;
        }

        __threadfence();
        __syncthreads();
        if (tid == 0) {
            const unsigned target = (s & 1) ? 0u : 1u;
            unsigned old = atomicAdd(&g_bar_ctr, 1u);
            if (old == GRID - 1) {
                atomicExch(&g_bar_ctr, 0u);
                __threadfence();
                g_bar_flag = target;
            } else {
                while (g_bar_flag != target) { }
            }
            __threadfence();
        }
        __syncthreads();
    }
}

// ============================================================================
// Launch
// ============================================================================
extern "C" void kernel_launch(void* const* d_in, const int* in_sizes, int n_in,
                              void* d_out, int out_size)
{
    const float* layer_input = (const float*)d_in[0];  // [S,B,D]
    const float* h_t         = (const float*)d_in[1];  // [B,H]
    const float* c_t         = (const float*)d_in[2];  // [B,H]
    const float* U           = (const float*)d_in[3];  // [4H,D]
    const float* V           = (const float*)d_in[4];  // [4H,H]
    const float* bih         = (const float*)d_in[5];  // [4H]
    const float* bhh         = (const float*)d_in[6];  // [4H]

    float* out = (float*)d_out;
    float* all_h1 = out;
    float* h_f    = out + (size_t)SS * BH;
    float* c_f    = h_f + BH;
    float* all_h2 = c_f + BH;
    float* all_c  = all_h2 + (size_t)SS * BH;

    float* Xp = nullptr;
    cudaGetSymbolAddress((void**)&Xp, g_X);
    __nv_bfloat16 *Ahi, *Alo, *Uhi, *Ulo;
    cudaGetSymbolAddress((void**)&Ahi, g_Ahi);
    cudaGetSymbolAddress((void**)&Alo, g_Alo);
    cudaGetSymbolAddress((void**)&Uhi, g_Uhi);
    cudaGetSymbolAddress((void**)&Ulo, g_Ulo);

    cudaFuncSetAttribute(lstm_persistent,
                         cudaFuncAttributeMaxDynamicSharedMemorySize, PERS_SMEM);

    // 0) bf16 hi/lo splits
    const int nA4 = SS * BB * DD / 4;   // 4,194,304
    const int nU4 = G4H * DD / 4;       // 1,048,576
    split_bf16<<<nA4 / 256, 256>>>(layer_input, Ahi, Alo, nA4);
    split_bf16<<<nU4 / 256, 256>>>(U, Uhi, Ulo, nU4);

    // 1) HMMA input projection + bias
    dim3 gg(G4H / 128, (SS * BB) / 128);   // (32, 128)
    gemm_x_hmma<<<gg, 256>>>(Ahi, Alo, Uhi, Ulo, bih, bhh, Xp);

    // 2) persistent recurrence (all 512 steps)
    lstm_persistent<<<GRID, 256, PERS_SMEM>>>(
        Xp, h_t, c_t, V, all_h1, all_h2, all_c, h_f, c_f);
}

// round 10
// speedup vs baseline: 2.9886x; 1.0047x over previous
#include <cuda_runtime.h>
#include <cuda_bf16.h>
#include <math.h>
#include <stdint.h>

// Problem constants
#define SS   512
#define BB   32
#define DD   1024
#define HH   1024
#define G4H  4096          // 4*H
#define BH   (BB*HH)       // 32768
#define GRID 128

typedef unsigned long long ull;

// packed fp32x2 FMA (Blackwell): d.xy += a.xy * b.xy
#define FFMA2(d, a, b) asm("fma.rn.f32x2 %0, %1, %2, %0;" : "+l"(d) : "l"(a), "l"(b))

// ldmatrix x4 (non-transposed, b16)
#define LDSM_X4(r0, r1, r2, r3, addr) \
    asm volatile("ldmatrix.sync.aligned.m8n8.x4.shared.b16 {%0,%1,%2,%3}, [%4];" \
                 : "=r"(r0), "=r"(r1), "=r"(r2), "=r"(r3) : "r"(addr))

// HMMA m16n8k16 bf16 -> f32
#define MMA16816(d, a, b) \
    asm volatile("mma.sync.aligned.m16n8k16.row.col.f32.bf16.bf16.f32 " \
                 "{%0,%1,%2,%3}, {%4,%5,%6,%7}, {%8,%9}, {%0,%1,%2,%3};" \
                 : "+f"((d)[0]), "+f"((d)[1]), "+f"((d)[2]), "+f"((d)[3]) \
                 : "r"((a)[0]), "r"((a)[1]), "r"((a)[2]), "r"((a)[3]), \
                   "r"((b)[0]), "r"((b)[1]))

// ---------------- scratch ---------------------------------------------------
__device__ float g_X[(size_t)SS * BB * G4H];             // 256 MB
__device__ __nv_bfloat16 g_Ahi[(size_t)SS * BB * DD];    // 32 MB
__device__ __nv_bfloat16 g_Alo[(size_t)SS * BB * DD];    // 32 MB
__device__ __nv_bfloat16 g_Uhi[(size_t)G4H * DD];        // 8 MB
__device__ __nv_bfloat16 g_Ulo[(size_t)G4H * DD];        // 8 MB

// ---------------- global barrier state (returns to 0 after every run) ------
__device__ unsigned g_bar_ctr = 0;
__device__ volatile unsigned g_bar_flag = 0;

__device__ __forceinline__ uint32_t smem_u32(const void* p) {
    uint32_t a;
    asm("{ .reg .u64 t; cvta.to.shared.u64 t, %1; cvt.u32.u64 %0, t; }"
        : "=r"(a) : "l"(p));
    return a;
}

// ============================================================================
// Split fp32 -> bf16 (hi, lo):  x = hi + lo + O(2^-18 x)
// ============================================================================
__global__ void __launch_bounds__(256) split_bf16(
    const float* __restrict__ src,
    __nv_bfloat16* __restrict__ hi,
    __nv_bfloat16* __restrict__ lo,
    int n4)
{
    int i = blockIdx.x * 256 + threadIdx.x;
    if (i >= n4) return;
    float4 v = ((const float4*)src)[i];
    float vv[4] = {v.x, v.y, v.z, v.w};
    unsigned short hs[4], ls[4];
    #pragma unroll
    for (int j = 0; j < 4; j++) {
        __nv_bfloat16 h = __float2bfloat16(vv[j]);
        __nv_bfloat16 l = __float2bfloat16(vv[j] - __bfloat162float(h));
        hs[j] = *reinterpret_cast<unsigned short*>(&h);
        ls[j] = *reinterpret_cast<unsigned short*>(&l);
    }
    uint2 ph, pl;
    ph.x = (uint32_t)hs[0] | ((uint32_t)hs[1] << 16);
    ph.y = (uint32_t)hs[2] | ((uint32_t)hs[3] << 16);
    pl.x = (uint32_t)ls[0] | ((uint32_t)ls[1] << 16);
    pl.y = (uint32_t)ls[2] | ((uint32_t)ls[3] << 16);
    ((uint2*)hi)[i] = ph;
    ((uint2*)lo)[i] = pl;
}

// ============================================================================
// Kernel A: HMMA (mma.sync m16n8k16 bf16) GEMM  (unchanged from R9, proven)
// ============================================================================
#define RPAD 40   // halves per smem row (32 data + 8 pad)

__global__ void __launch_bounds__(256) gemm_x_hmma(
    const __nv_bfloat16* __restrict__ Ahi, const __nv_bfloat16* __restrict__ Alo,
    const __nv_bfloat16* __restrict__ Bhi, const __nv_bfloat16* __restrict__ Blo,
    const float* __restrict__ bih, const float* __restrict__ bhh,
    float* __restrict__ X)
{
    __shared__ __align__(16) unsigned short sAhi[128 * RPAD];
    __shared__ __align__(16) unsigned short sAlo[128 * RPAD];
    __shared__ __align__(16) unsigned short sBhi[128 * RPAD];
    __shared__ __align__(16) unsigned short sBlo[128 * RPAD];
    __shared__ float bias_s[128];

    const int tid  = threadIdx.x;
    const int lane = tid & 31;
    const int wid  = tid >> 5;
    const int wm   = (wid >> 1) * 32;
    const int wn   = (wid & 1) * 64;

    const int bn = blockIdx.x * 128;
    const int bm = blockIdx.y * 128;

    if (tid < 128) bias_s[tid] = bih[bn + tid] + bhh[bn + tid];

    const int seg0 = tid * 2;
    const int row0s = seg0 >> 2, sk0 = (seg0 & 3) * 8;
    const int row1s = (seg0 + 1) >> 2, sk1 = ((seg0 + 1) & 3) * 8;

    const __nv_bfloat16* gsrc[4] = {
        Ahi + (size_t)bm * DD, Alo + (size_t)bm * DD,
        Bhi + (size_t)bn * DD, Blo + (size_t)bn * DD };
    unsigned short* stile[4] = { sAhi, sAlo, sBhi, sBlo };

    const uint32_t aoff = (uint32_t)(lane & 15) * (RPAD * 2) + (uint32_t)(lane >> 4) * 16;
    const uint32_t boff = ((uint32_t)((lane & 7) + (lane >> 4) * 8)) * (RPAD * 2)
                        + (uint32_t)((lane >> 3) & 1) * 16;

    const uint32_t sbAhi = smem_u32(sAhi), sbAlo = smem_u32(sAlo);
    const uint32_t sbBhi = smem_u32(sBhi), sbBlo = smem_u32(sBlo);

    float acc[2][8][4];
    #pragma unroll
    for (int im = 0; im < 2; im++)
        #pragma unroll
        for (int ia = 0; ia < 8; ia++)
            #pragma unroll
            for (int q = 0; q < 4; q++) acc[im][ia][q] = 0.f;

    for (int kc = 0; kc < 32; kc++) {
        uint4 v0[4], v1[4];
        #pragma unroll
        for (int t = 0; t < 4; t++) {
            v0[t] = *(const uint4*)(gsrc[t] + (size_t)row0s * DD + kc * 32 + sk0);
            v1[t] = *(const uint4*)(gsrc[t] + (size_t)row1s * DD + kc * 32 + sk1);
        }
        __syncthreads();
        #pragma unroll
        for (int t = 0; t < 4; t++) {
            *(uint4*)&stile[t][row0s * RPAD + sk0] = v0[t];
            *(uint4*)&stile[t][row1s * RPAD + sk1] = v1[t];
        }
        __syncthreads();

        #pragma unroll
        for (int ks2 = 0; ks2 < 2; ks2++) {
            const uint32_t kb = ks2 * 32;

            uint32_t ah[2][4], al[2][4];
            #pragma unroll
            for (int im = 0; im < 2; im++) {
                const uint32_t ro = (uint32_t)(wm + im * 16) * (RPAD * 2) + kb;
                LDSM_X4(ah[im][0], ah[im][1], ah[im][2], ah[im][3], sbAhi + ro + aoff);
                LDSM_X4(al[im][0], al[im][1], al[im][2], al[im][3], sbAlo + ro + aoff);
            }
            uint32_t bh[4][4], bl[4][4];
            #pragma unroll
            for (int g = 0; g < 4; g++) {
                const uint32_t ro = (uint32_t)(wn + g * 16) * (RPAD * 2) + kb;
                LDSM_X4(bh[g][0], bh[g][1], bh[g][2], bh[g][3], sbBhi + ro + boff);
                LDSM_X4(bl[g][0], bl[g][1], bl[g][2], bl[g][3], sbBlo + ro + boff);
            }

            #pragma unroll
            for (int im = 0; im < 2; im++)
                #pragma unroll
                for (int g = 0; g < 4; g++)
                    #pragma unroll
                    for (int h = 0; h < 2; h++) {
                        const int ia = 2 * g + h;
                        uint32_t bhf[2] = { bh[g][h * 2], bh[g][h * 2 + 1] };
                        uint32_t blf[2] = { bl[g][h * 2], bl[g][h * 2 + 1] };
                        MMA16816(acc[im][ia], ah[im], bhf);
                        MMA16816(acc[im][ia], ah[im], blf);
                        MMA16816(acc[im][ia], al[im], bhf);
                    }
        }
    }

    const int trow = lane >> 2;
    const int tcol = (lane & 3) * 2;
    #pragma unroll
    for (int im = 0; im < 2; im++) {
        #pragma unroll
        for (int ia = 0; ia < 8; ia++) {
            const int nloc = wn + ia * 8 + tcol;
            const float b0 = bias_s[nloc], b1 = bias_s[nloc + 1];
            const size_t r0 = (size_t)(bm + wm + im * 16 + trow) * G4H + bn + nloc;
            const size_t r1 = r0 + (size_t)8 * G4H;
            float2 o0 = { acc[im][ia][0] + b0, acc[im][ia][1] + b1 };
            float2 o1 = { acc[im][ia][2] + b0, acc[im][ia][3] + b1 };
            *(float2*)&X[r0] = o0;
            *(float2*)&X[r1] = o1;
        }
    }
}

// ============================================================================
// Kernel B: PERSISTENT LSTM — 512 threads (16 warps, 4/SMSP).
//   Thread tile: 2 rows x 32 k. lane: rp = lane&15 -> rows {rp, rp+16};
//   ksub = lane>>4 -> k-slice ks = 2*warp + ksub (32 k each).
//   Per-warp self-staging of its k-64 region (syncwarp, not syncthreads).
//   h_s [32 ks][32 b][32], ks-stride 1032 floats (== 8 banks): the warp's two
//   broadcast LDS addresses hit distinct bank quads. Fold = shfl_xor(16).
//   pb [16 w][32 rows][33 b]. c state in regs of threads 0..255.
// ============================================================================
#define PTHREADS  512
#define KSTR      1032                        // 32*32 + 8
#define SM_H      (32 * KSTR)                 // 33024 floats
#define SM_PB     (16 * 32 * 33)              // 16896 floats
#define SM_XG     (4 * 32 * 8)                // 1024 floats
#define PERS_SMEM ((SM_H + SM_PB + SM_XG) * 4)   // 203776 B

__device__ __forceinline__ float fsig(float x) {
    return __fdividef(1.f, 1.f + __expf(-x));
}
__device__ __forceinline__ float ftanh(float x) {
    float e = __expf(-2.f * x);
    return __fdividef(1.f - e, 1.f + e);
}

__global__ void __launch_bounds__(PTHREADS, 1) lstm_persistent(
    const float* __restrict__ X,
    const float* __restrict__ h0,
    const float* __restrict__ c0,
    const float* __restrict__ V,
    float* __restrict__ all_h1,
    float* __restrict__ all_h2,
    float* __restrict__ all_c,
    float* __restrict__ h_f,
    float* __restrict__ c_f)
{
    extern __shared__ float sm[];
    float* h_s  = sm;                 // [32 ks][32 b][32] stride KSTR per ks
    float* pb   = sm + SM_H;          // [16 w][32 rows][33 b]
    float* xg_s = pb + SM_PB;         // [4 g][32 b][8 c]

    const int tid  = threadIdx.x;
    const int cb   = blockIdx.x;
    const int lane = tid & 31;
    const int w    = tid >> 5;        // warp 0..15, owns k [w*64, w*64+64)

    const int rp   = lane & 15;       // rows rp, rp+16
    const int ksub = lane >> 4;       // 0/1

    // ---- combine mapping (threads 0..255) ----
    const int cbb = tid >> 3;         // batch (tid<256)
    const int ccc = tid & 7;          // column
    const int ooff = cbb * HH + cb * 8 + ccc;

    // ---- V tile in regs: 2 rows x 32 k = 16 ull each ----
    ull vreg[2][16];
    #pragma unroll
    for (int r = 0; r < 2; r++) {
        const int lrow = rp + 16 * r;
        const size_t grow = (size_t)(lrow >> 3) * HH + cb * 8 + (lrow & 7);
        const ulonglong2* vp =
            (const ulonglong2*)(V + grow * HH + w * 64 + ksub * 32);
        #pragma unroll
        for (int q = 0; q < 8; q++) {
            ulonglong2 u = vp[q];
            vreg[r][2 * q]     = u.x;
            vreg[r][2 * q + 1] = u.y;
        }
    }

    float c_reg = (tid < 256) ? c0[ooff] : 0.f;
    const float* hbase = h_s + (2 * w + ksub) * KSTR;

    // Xg mapping (tid<256): g=tid&3, half=(tid>>2)&1, b=tid>>3
    const int xg_g = tid & 3, xg_half = (tid >> 2) & 1, xg_b = tid >> 3;
    const float* xsrc = X + (size_t)xg_b * G4H + (size_t)xg_g * HH
                          + cb * 8 + xg_half * 4;

    for (int s = 0; s < SS; s++) {
        // ---- Xg prefetch (independent of h) ----
        float4 xv;
        if (tid < 256) xv = *(const float4*)(xsrc + (size_t)s * BB * G4H);

        // ---- per-warp h staging: warp w stages k in [w*64, w*64+64) ----
        const float4* hp4 = (const float4*)((s == 0) ? h0
                              : (all_h1 + (size_t)(s - 1) * BH));
        #pragma unroll
        for (int it = 0; it < 16; it++) {
            const int idx = it * 32 + lane;
            const int b   = idx >> 4;        // 0..31
            const int k4l = idx & 15;        // float4 within k-64
            float4 v = hp4[b * 256 + w * 16 + k4l];
            const int ksl = k4l >> 3;        // 0/1
            const int kk  = (k4l & 7) * 4;
            *(float4*)&h_s[(2 * w + ksl) * KSTR + b * 32 + kk] = v;
        }
        if (tid < 256)
            *(float4*)&xg_s[(xg_g * 32 + xg_b) * 8 + xg_half * 4] = xv;
        __syncwarp();

        // ---- compute: 16 batch pairs ----
        for (int b2 = 0; b2 < 32; b2 += 2) {
            const ulonglong2* hp0 = (const ulonglong2*)(hbase + b2 * 32);
            const ulonglong2* hp1 = (const ulonglong2*)(hbase + b2 * 32 + 32);
            ull a00 = 0ULL, a01 = 0ULL, a10 = 0ULL, a11 = 0ULL;
            #pragma unroll
            for (int q = 0; q < 8; q++) {
                ulonglong2 hx = hp0[q];
                ulonglong2 hy = hp1[q];
                FFMA2(a00, vreg[0][2 * q],     hx.x);
                FFMA2(a10, vreg[1][2 * q],     hx.x);
                FFMA2(a01, vreg[0][2 * q],     hy.x);
                FFMA2(a11, vreg[1][2 * q],     hy.x);
                FFMA2(a00, vreg[0][2 * q + 1], hx.y);
                FFMA2(a10, vreg[1][2 * q + 1], hx.y);
                FFMA2(a01, vreg[0][2 * q + 1], hy.y);
                FFMA2(a11, vreg[1][2 * q + 1], hy.y);
            }
            float2 f;
            f = *(float2*)&a00; float s00 = f.x + f.y;
            f = *(float2*)&a10; float s10 = f.x + f.y;
            f = *(float2*)&a01; float s01 = f.x + f.y;
            f = *(float2*)&a11; float s11 = f.x + f.y;

            // fold the two k-slices (lanes l and l^16 share rp)
            s00 += __shfl_xor_sync(0xffffffffu, s00, 16);
            s10 += __shfl_xor_sync(0xffffffffu, s10, 16);
            s01 += __shfl_xor_sync(0xffffffffu, s01, 16);
            s11 += __shfl_xor_sync(0xffffffffu, s11, 16);

            if (lane < 16) {
                const int b0 = (w * 32 + rp) * 33;
                const int b1 = (w * 32 + rp + 16) * 33;
                pb[b0 + b2]     = s00;
                pb[b1 + b2]     = s10;
                pb[b0 + b2 + 1] = s01;
                pb[b1 + b2 + 1] = s11;
            }
        }
        __syncthreads();

        // ---- combine + cell (threads 0..255) ----
        if (tid < 256) {
            float g4[4];
            #pragma unroll
            for (int g = 0; g < 4; g++) {
                const int lrr = g * 8 + ccc;
                float acc = xg_s[(g * 32 + cbb) * 8 + ccc];
                #pragma unroll
                for (int k2 = 0; k2 < 16; k2++)
                    acc += pb[(k2 * 32 + lrr) * 33 + cbb];
                g4[g] = acc;
            }

            const float iv = fsig(g4[0]);
            const float fv = fsig(g4[1]);
            const float gg = ftanh(g4[2]);
            const float ov = fsig(g4[3]);

            c_reg = fv * c_reg + iv * gg;
            const float hn = ov * ftanh(c_reg);

            all_h1[(size_t)s * BH + ooff] = hn;
            all_h2[(size_t)s * BH + ooff] = hn;
            all_c [(size_t)s * BH + ooff] = c_reg;
            if (s == SS - 1) {
                h_f[ooff] = hn;
                c_f[ooff] = c_reg;
            }
        }

        // ---- grid barrier (sense-reversing; returns to 0 each run) ----
        __threadfence();
        __syncthreads();
        if (tid == 0) {
            const unsigned target = (s & 1) ? 0u : 1u;
            unsigned old = atomicAdd(&g_bar_ctr, 1u);
            if (old == GRID - 1) {
                atomicExch(&g_bar_ctr, 0u);
                __threadfence();
                g_bar_flag = target;
            } else {
                while (g_bar_flag != target) { }
            }
            __threadfence();
        }
        __syncthreads();
    }
}

// ============================================================================
// Launch
// ============================================================================
extern "C" void kernel_launch(void* const* d_in, const int* in_sizes, int n_in,
                              void* d_out, int out_size)
{
    const float* layer_input = (const float*)d_in[0];  // [S,B,D]
    const float* h_t         = (const float*)d_in[1];  // [B,H]
    const float* c_t         = (const float*)d_in[2];  // [B,H]
    const float* U           = (const float*)d_in[3];  // [4H,D]
    const float* V           = (const float*)d_in[4];  // [4H,H]
    const float* bih         = (const float*)d_in[5];  // [4H]
    const float* bhh         = (const float*)d_in[6];  // [4H]

    float* out = (float*)d_out;
    float* all_h1 = out;
    float* h_f    = out + (size_t)SS * BH;
    float* c_f    = h_f + BH;
    float* all_h2 = c_f + BH;
    float* all_c  = all_h2 + (size_t)SS * BH;

    float* Xp = nullptr;
    cudaGetSymbolAddress((void**)&Xp, g_X);
    __nv_bfloat16 *Ahi, *Alo, *Uhi, *Ulo;
    cudaGetSymbolAddress((void**)&Ahi, g_Ahi);
    cudaGetSymbolAddress((void**)&Alo, g_Alo);
    cudaGetSymbolAddress((void**)&Uhi, g_Uhi);
    cudaGetSymbolAddress((void**)&Ulo, g_Ulo);

    cudaFuncSetAttribute(lstm_persistent,
                         cudaFuncAttributeMaxDynamicSharedMemorySize, PERS_SMEM);

    // 0) bf16 hi/lo splits
    const int nA4 = SS * BB * DD / 4;
    const int nU4 = G4H * DD / 4;
    split_bf16<<<nA4 / 256, 256>>>(layer_input, Ahi, Alo, nA4);
    split_bf16<<<nU4 / 256, 256>>>(U, Uhi, Ulo, nU4);

    // 1) HMMA input projection + bias
    dim3 gg(G4H / 128, (SS * BB) / 128);   // (32, 128)
    gemm_x_hmma<<<gg, 256>>>(Ahi, Alo, Uhi, Ulo, bih, bhh, Xp);

    // 2) persistent recurrence (all 512 steps)
    lstm_persistent<<<GRID, PTHREADS, PERS_SMEM>>>(
        Xp, h_t, c_t, V, all_h1, all_h2, all_c, h_f, c_f);
}

// round 11
// speedup vs baseline: 4.5567x; 1.5247x over previous
#include <cuda_runtime.h>
#include <cuda_bf16.h>
#include <math.h>
#include <stdint.h>

// Problem constants
#define SS   512
#define BB   32
#define DD   1024
#define HH   1024
#define G4H  4096          // 4*H
#define BH   (BB*HH)       // 32768
#define GRID 128

typedef unsigned long long ull;

// ldmatrix x4 (non-transposed, b16)
#define LDSM_X4(r0, r1, r2, r3, addr) \
    asm volatile("ldmatrix.sync.aligned.m8n8.x4.shared.b16 {%0,%1,%2,%3}, [%4];" \
                 : "=r"(r0), "=r"(r1), "=r"(r2), "=r"(r3) : "r"(addr))

// HMMA m16n8k16 bf16 -> f32
#define MMA16816(d, a, b) \
    asm volatile("mma.sync.aligned.m16n8k16.row.col.f32.bf16.bf16.f32 " \
                 "{%0,%1,%2,%3}, {%4,%5,%6,%7}, {%8,%9}, {%0,%1,%2,%3};" \
                 : "+f"((d)[0]), "+f"((d)[1]), "+f"((d)[2]), "+f"((d)[3]) \
                 : "r"((a)[0]), "r"((a)[1]), "r"((a)[2]), "r"((a)[3]), \
                   "r"((b)[0]), "r"((b)[1]))

// ---------------- scratch ---------------------------------------------------
__device__ float g_X[(size_t)SS * BB * G4H];             // 256 MB
__device__ __nv_bfloat16 g_Ahi[(size_t)SS * BB * DD];
__device__ __nv_bfloat16 g_Alo[(size_t)SS * BB * DD];
__device__ __nv_bfloat16 g_Uhi[(size_t)G4H * DD];
__device__ __nv_bfloat16 g_Ulo[(size_t)G4H * DD];
__device__ __nv_bfloat16 g_Vhi[(size_t)G4H * HH];
__device__ __nv_bfloat16 g_Vlo[(size_t)G4H * HH];
__device__ __nv_bfloat16 g_hhi[BH];                      // live h state, bf16 hi
__device__ __nv_bfloat16 g_hlo[BH];                      // live h state, bf16 lo

// ---------------- global barrier state (returns to 0 after every run) ------
__device__ unsigned g_bar_ctr = 0;
__device__ volatile unsigned g_bar_flag = 0;

__device__ __forceinline__ uint32_t smem_u32(const void* p) {
    uint32_t a;
    asm("{ .reg .u64 t; cvta.to.shared.u64 t, %1; cvt.u32.u64 %0, t; }"
        : "=r"(a) : "l"(p));
    return a;
}

// ============================================================================
// Split fp32 -> bf16 (hi, lo):  x = hi + lo + O(2^-18 x)
// ============================================================================
__global__ void __launch_bounds__(256) split_bf16(
    const float* __restrict__ src,
    __nv_bfloat16* __restrict__ hi,
    __nv_bfloat16* __restrict__ lo,
    int n4)
{
    int i = blockIdx.x * 256 + threadIdx.x;
    if (i >= n4) return;
    float4 v = ((const float4*)src)[i];
    float vv[4] = {v.x, v.y, v.z, v.w};
    unsigned short hs[4], ls[4];
    #pragma unroll
    for (int j = 0; j < 4; j++) {
        __nv_bfloat16 h = __float2bfloat16(vv[j]);
        __nv_bfloat16 l = __float2bfloat16(vv[j] - __bfloat162float(h));
        hs[j] = *reinterpret_cast<unsigned short*>(&h);
        ls[j] = *reinterpret_cast<unsigned short*>(&l);
    }
    uint2 ph, pl;
    ph.x = (uint32_t)hs[0] | ((uint32_t)hs[1] << 16);
    ph.y = (uint32_t)hs[2] | ((uint32_t)hs[3] << 16);
    pl.x = (uint32_t)ls[0] | ((uint32_t)ls[1] << 16);
    pl.y = (uint32_t)ls[2] | ((uint32_t)ls[3] << 16);
    ((uint2*)hi)[i] = ph;
    ((uint2*)lo)[i] = pl;
}

// ============================================================================
// Kernel A: HMMA GEMM  X = A @ U^T + bias  (unchanged from R9, proven)
// ============================================================================
#define RPAD 40

__global__ void __launch_bounds__(256) gemm_x_hmma(
    const __nv_bfloat16* __restrict__ Ahi, const __nv_bfloat16* __restrict__ Alo,
    const __nv_bfloat16* __restrict__ Bhi, const __nv_bfloat16* __restrict__ Blo,
    const float* __restrict__ bih, const float* __restrict__ bhh,
    float* __restrict__ X)
{
    __shared__ __align__(16) unsigned short sAhi[128 * RPAD];
    __shared__ __align__(16) unsigned short sAlo[128 * RPAD];
    __shared__ __align__(16) unsigned short sBhi[128 * RPAD];
    __shared__ __align__(16) unsigned short sBlo[128 * RPAD];
    __shared__ float bias_s[128];

    const int tid  = threadIdx.x;
    const int lane = tid & 31;
    const int wid  = tid >> 5;
    const int wm   = (wid >> 1) * 32;
    const int wn   = (wid & 1) * 64;

    const int bn = blockIdx.x * 128;
    const int bm = blockIdx.y * 128;

    if (tid < 128) bias_s[tid] = bih[bn + tid] + bhh[bn + tid];

    const int seg0 = tid * 2;
    const int row0s = seg0 >> 2, sk0 = (seg0 & 3) * 8;
    const int row1s = (seg0 + 1) >> 2, sk1 = ((seg0 + 1) & 3) * 8;

    const __nv_bfloat16* gsrc[4] = {
        Ahi + (size_t)bm * DD, Alo + (size_t)bm * DD,
        Bhi + (size_t)bn * DD, Blo + (size_t)bn * DD };
    unsigned short* stile[4] = { sAhi, sAlo, sBhi, sBlo };

    const uint32_t aoff = (uint32_t)(lane & 15) * (RPAD * 2) + (uint32_t)(lane >> 4) * 16;
    const uint32_t boff = ((uint32_t)((lane & 7) + (lane >> 4) * 8)) * (RPAD * 2)
                        + (uint32_t)((lane >> 3) & 1) * 16;

    const uint32_t sbAhi = smem_u32(sAhi), sbAlo = smem_u32(sAlo);
    const uint32_t sbBhi = smem_u32(sBhi), sbBlo = smem_u32(sBlo);

    float acc[2][8][4];
    #pragma unroll
    for (int im = 0; im < 2; im++)
        #pragma unroll
        for (int ia = 0; ia < 8; ia++)
            #pragma unroll
            for (int q = 0; q < 4; q++) acc[im][ia][q] = 0.f;

    for (int kc = 0; kc < 32; kc++) {
        uint4 v0[4], v1[4];
        #pragma unroll
        for (int t = 0; t < 4; t++) {
            v0[t] = *(const uint4*)(gsrc[t] + (size_t)row0s * DD + kc * 32 + sk0);
            v1[t] = *(const uint4*)(gsrc[t] + (size_t)row1s * DD + kc * 32 + sk1);
        }
        __syncthreads();
        #pragma unroll
        for (int t = 0; t < 4; t++) {
            *(uint4*)&stile[t][row0s * RPAD + sk0] = v0[t];
            *(uint4*)&stile[t][row1s * RPAD + sk1] = v1[t];
        }
        __syncthreads();

        #pragma unroll
        for (int ks2 = 0; ks2 < 2; ks2++) {
            const uint32_t kb = ks2 * 32;

            uint32_t ah[2][4], al[2][4];
            #pragma unroll
            for (int im = 0; im < 2; im++) {
                const uint32_t ro = (uint32_t)(wm + im * 16) * (RPAD * 2) + kb;
                LDSM_X4(ah[im][0], ah[im][1], ah[im][2], ah[im][3], sbAhi + ro + aoff);
                LDSM_X4(al[im][0], al[im][1], al[im][2], al[im][3], sbAlo + ro + aoff);
            }
            uint32_t bh[4][4], bl[4][4];
            #pragma unroll
            for (int g = 0; g < 4; g++) {
                const uint32_t ro = (uint32_t)(wn + g * 16) * (RPAD * 2) + kb;
                LDSM_X4(bh[g][0], bh[g][1], bh[g][2], bh[g][3], sbBhi + ro + boff);
                LDSM_X4(bl[g][0], bl[g][1], bl[g][2], bl[g][3], sbBlo + ro + boff);
            }

            #pragma unroll
            for (int im = 0; im < 2; im++)
                #pragma unroll
                for (int g = 0; g < 4; g++)
                    #pragma unroll
                    for (int h = 0; h < 2; h++) {
                        const int ia = 2 * g + h;
                        uint32_t bhf[2] = { bh[g][h * 2], bh[g][h * 2 + 1] };
                        uint32_t blf[2] = { bl[g][h * 2], bl[g][h * 2 + 1] };
                        MMA16816(acc[im][ia], ah[im], bhf);
                        MMA16816(acc[im][ia], ah[im], blf);
                        MMA16816(acc[im][ia], al[im], bhf);
                    }
        }
    }

    const int trow = lane >> 2;
    const int tcol = (lane & 3) * 2;
    #pragma unroll
    for (int im = 0; im < 2; im++) {
        #pragma unroll
        for (int ia = 0; ia < 8; ia++) {
            const int nloc = wn + ia * 8 + tcol;
            const float b0 = bias_s[nloc], b1 = bias_s[nloc + 1];
            const size_t r0 = (size_t)(bm + wm + im * 16 + trow) * G4H + bn + nloc;
            const size_t r1 = r0 + (size_t)8 * G4H;
            float2 o0 = { acc[im][ia][0] + b0, acc[im][ia][1] + b1 };
            float2 o1 = { acc[im][ia][2] + b0, acc[im][ia][3] + b1 };
            *(float2*)&X[r0] = o0;
            *(float2*)&X[r1] = o1;
        }
    }
}

// ============================================================================
// Kernel B: PERSISTENT LSTM — HMMA recurrence.
//   512 thr (16 warps = 2 m-halves x 8 k-slices of 128).
//   gates[32 rows][32 b] = V[32][1024] . h[1024][32] via mma m16n8k16,
//   bf16 hi/lo x hi/lo (3 products). V fragments live in registers.
//   h staged per step from g_hhi/g_hlo (written by previous step's cell).
//   Split-k 8 partials -> pb[8][32][34] -> combine + cell (c in regs).
// ============================================================================
#define PTHREADS  512
#define HROWB     2064                 // bytes per h smem row (2048 + 16 pad)
#define OFF_HHI   0
#define OFF_HLO   (32 * HROWB)                 // 66048
#define OFF_PB    (2 * 32 * HROWB)             // 132096
#define OFF_XG    (OFF_PB + 8 * 32 * 34 * 4)   // +34816 = 166912
#define PERS_SMEM (OFF_XG + 4 * 32 * 8 * 4)    // +4096 = 171008

__device__ __forceinline__ float fsig(float x) {
    return __fdividef(1.f, 1.f + __expf(-x));
}
__device__ __forceinline__ float ftanh(float x) {
    float e = __expf(-2.f * x);
    return __fdividef(1.f - e, 1.f + e);
}

__global__ void __launch_bounds__(PTHREADS, 1) lstm_persistent(
    const float* __restrict__ X,
    const float* __restrict__ c0,
    const __nv_bfloat16* __restrict__ Vhi,
    const __nv_bfloat16* __restrict__ Vlo,
    __nv_bfloat16* __restrict__ hhi,
    __nv_bfloat16* __restrict__ hlo,
    float* __restrict__ all_h1,
    float* __restrict__ all_h2,
    float* __restrict__ all_c,
    float* __restrict__ h_f,
    float* __restrict__ c_f)
{
    extern __shared__ char smx[];
    float* pb   = (float*)(smx + OFF_PB);    // [8 wk][32 rows][34 b]
    float* xg_s = (float*)(smx + OFF_XG);    // [4 g][32 b][8 c]

    const int tid  = threadIdx.x;
    const int cb   = blockIdx.x;
    const int lane = tid & 31;
    const int w    = tid >> 5;       // warp 0..15
    const int wm   = w & 1;          // m-half: rows [16wm, 16wm+16)
    const int wk   = w >> 1;         // k-slice: [wk*128, wk*128+128)

    // ---- combine/cell mapping (threads 0..255) ----
    const int cbb = tid >> 3;        // batch
    const int ccc = tid & 7;         // column
    const int ooff = cbb * HH + cb * 8 + ccc;

    // ---- V fragments in registers: A-frag m16k16, 8 ksteps, hi+lo ----
    // a0: (row0, k0), a1: (row0+8, k0), a2: (row0, k+8), a3: (row0+8, k+8)
    uint32_t vhi[8][4], vlo[8][4];
    {
        const int lr0 = 16 * wm + (lane >> 2);
        const int lr1 = lr0 + 8;
        const size_t gr0 = (size_t)(lr0 >> 3) * HH + cb * 8 + (lr0 & 7);
        const size_t gr1 = (size_t)(lr1 >> 3) * HH + cb * 8 + (lr1 & 7);
        const int kb0 = wk * 128 + (lane & 3) * 2;
        #pragma unroll
        for (int ks = 0; ks < 8; ks++) {
            const int k = kb0 + ks * 16;
            vhi[ks][0] = *(const uint32_t*)(Vhi + gr0 * HH + k);
            vhi[ks][1] = *(const uint32_t*)(Vhi + gr1 * HH + k);
            vhi[ks][2] = *(const uint32_t*)(Vhi + gr0 * HH + k + 8);
            vhi[ks][3] = *(const uint32_t*)(Vhi + gr1 * HH + k + 8);
            vlo[ks][0] = *(const uint32_t*)(Vlo + gr0 * HH + k);
            vlo[ks][1] = *(const uint32_t*)(Vlo + gr1 * HH + k);
            vlo[ks][2] = *(const uint32_t*)(Vlo + gr0 * HH + k + 8);
            vlo[ks][3] = *(const uint32_t*)(Vlo + gr1 * HH + k + 8);
        }
    }

    float c_reg = (tid < 256) ? c0[ooff] : 0.f;

    // ldmatrix B addresses (h): row = batch, cols = k (non-transposed)
    const uint32_t sb = smem_u32(smx);
    const uint32_t lm_row = (lane & 7) + ((lane >> 4) & 1) * 8;
    const uint32_t lm_k16 = ((lane >> 3) & 1) * 16;
    const uint32_t bhi_g0 = sb + OFF_HHI + lm_row * HROWB + lm_k16 + wk * 256;
    const uint32_t bhi_g1 = bhi_g0 + 16 * HROWB;
    const uint32_t blo_g0 = bhi_g0 + OFF_HLO;
    const uint32_t blo_g1 = bhi_g1 + OFF_HLO;

    // Xg mapping (tid<256)
    const int xg_g = tid & 3, xg_half = (tid >> 2) & 1, xg_b = tid >> 3;
    const float* xsrc = X + (size_t)xg_b * G4H + (size_t)xg_g * HH
                          + cb * 8 + xg_half * 4;

    for (int s = 0; s < SS; s++) {
        // ---- Xg prefetch ----
        float4 xv;
        if (tid < 256) xv = *(const float4*)(xsrc + (size_t)s * BB * G4H);

        // ---- stage h hi/lo: [32 b][1024] bf16 -> smem rows of 2064 B ----
        const uint4* shi = (const uint4*)hhi;   // 4096 uint4
        const uint4* slo = (const uint4*)hlo;
        #pragma unroll
        for (int it = 0; it < 8; it++) {
            const int idx = it * PTHREADS + tid;  // 0..4095
            const int b = idx >> 7, kc = idx & 127;
            *(uint4*)(smx + OFF_HHI + b * HROWB + kc * 16) = shi[idx];
        }
        #pragma unroll
        for (int it = 0; it < 8; it++) {
            const int idx = it * PTHREADS + tid;
            const int b = idx >> 7, kc = idx & 127;
            *(uint4*)(smx + OFF_HLO + b * HROWB + kc * 16) = slo[idx];
        }
        if (tid < 256)
            *(float4*)&xg_s[(xg_g * 32 + xg_b) * 8 + xg_half * 4] = xv;
        __syncthreads();

        // ---- HMMA: 8 ksteps x (4 LDSM.x4 + 12 MMA) ----
        float acc[4][4];
        #pragma unroll
        for (int nt = 0; nt < 4; nt++)
            #pragma unroll
            for (int q = 0; q < 4; q++) acc[nt][q] = 0.f;

        #pragma unroll
        for (int ks = 0; ks < 8; ks++) {
            const uint32_t kb = ks * 32;
            uint32_t h0[4], h1[4], l0[4], l1[4];
            LDSM_X4(h0[0], h0[1], h0[2], h0[3], bhi_g0 + kb);
            LDSM_X4(h1[0], h1[1], h1[2], h1[3], bhi_g1 + kb);
            LDSM_X4(l0[0], l0[1], l0[2], l0[3], blo_g0 + kb);
            LDSM_X4(l1[0], l1[1], l1[2], l1[3], blo_g1 + kb);
            // nt0: b0-7 {h0[0],h0[1]}, nt1: b8-15 {h0[2],h0[3]},
            // nt2: b16-23 {h1[0],h1[1]}, nt3: b24-31 {h1[2],h1[3]}
            MMA16816(acc[0], vhi[ks], &h0[0]);
            MMA16816(acc[0], vhi[ks], &l0[0]);
            MMA16816(acc[0], vlo[ks], &h0[0]);
            MMA16816(acc[1], vhi[ks], &h0[2]);
            MMA16816(acc[1], vhi[ks], &l0[2]);
            MMA16816(acc[1], vlo[ks], &h0[2]);
            MMA16816(acc[2], vhi[ks], &h1[0]);
            MMA16816(acc[2], vhi[ks], &l1[0]);
            MMA16816(acc[2], vlo[ks], &h1[0]);
            MMA16816(acc[3], vhi[ks], &h1[2]);
            MMA16816(acc[3], vhi[ks], &l1[2]);
            MMA16816(acc[3], vlo[ks], &h1[2]);
        }

        // ---- partials -> pb[wk][row][34] ----
        {
            const int prow = 16 * wm + (lane >> 2);
            const int pcol = (lane & 3) * 2;
            float* pw0 = pb + (wk * 32 + prow) * 34;
            float* pw1 = pw0 + 8 * 34;
            #pragma unroll
            for (int nt = 0; nt < 4; nt++) {
                float2 u = { acc[nt][0], acc[nt][1] };
                float2 v = { acc[nt][2], acc[nt][3] };
                *(float2*)&pw0[nt * 8 + pcol] = u;
                *(float2*)&pw1[nt * 8 + pcol] = v;
            }
        }
        __syncthreads();

        // ---- combine + cell (threads 0..255) ----
        if (tid < 256) {
            float g4[4];
            #pragma unroll
            for (int g = 0; g < 4; g++) {
                const int lrr = g * 8 + ccc;
                float acm = xg_s[(g * 32 + cbb) * 8 + ccc];
                #pragma unroll
                for (int k2 = 0; k2 < 8; k2++)
                    acm += pb[(k2 * 32 + lrr) * 34 + cbb];
                g4[g] = acm;
            }

            const float iv = fsig(g4[0]);
            const float fv = fsig(g4[1]);
            const float gg = ftanh(g4[2]);
            const float ov = fsig(g4[3]);

            c_reg = fv * c_reg + iv * gg;
            const float hn = ov * ftanh(c_reg);

            all_h1[(size_t)s * BH + ooff] = hn;
            all_h2[(size_t)s * BH + ooff] = hn;
            all_c [(size_t)s * BH + ooff] = c_reg;
            if (s == SS - 1) {
                h_f[ooff] = hn;
                c_f[ooff] = c_reg;
            }

            // live bf16 hi/lo state for next step
            __nv_bfloat16 hh = __float2bfloat16(hn);
            __nv_bfloat16 hl = __float2bfloat16(hn - __bfloat162float(hh));
            hhi[ooff] = hh;
            hlo[ooff] = hl;
        }

        // ---- grid barrier (sense-reversing; returns to 0 each run) ----
        __threadfence();
        __syncthreads();
        if (tid == 0) {
            const unsigned target = (s & 1) ? 0u : 1u;
            unsigned old = atomicAdd(&g_bar_ctr, 1u);
            if (old == GRID - 1) {
                atomicExch(&g_bar_ctr, 0u);
                __threadfence();
                g_bar_flag = target;
            } else {
                while (g_bar_flag != target) { }
            }
            __threadfence();
        }
        __syncthreads();
    }
}

// ============================================================================
// Launch
// ============================================================================
extern "C" void kernel_launch(void* const* d_in, const int* in_sizes, int n_in,
                              void* d_out, int out_size)
{
    const float* layer_input = (const float*)d_in[0];  // [S,B,D]
    const float* h_t         = (const float*)d_in[1];  // [B,H]
    const float* c_t         = (const float*)d_in[2];  // [B,H]
    const float* U           = (const float*)d_in[3];  // [4H,D]
    const float* V           = (const float*)d_in[4];  // [4H,H]
    const float* bih         = (const float*)d_in[5];  // [4H]
    const float* bhh         = (const float*)d_in[6];  // [4H]

    float* out = (float*)d_out;
    float* all_h1 = out;
    float* h_f    = out + (size_t)SS * BH;
    float* c_f    = h_f + BH;
    float* all_h2 = c_f + BH;
    float* all_c  = all_h2 + (size_t)SS * BH;

    float* Xp = nullptr;
    cudaGetSymbolAddress((void**)&Xp, g_X);
    __nv_bfloat16 *Ahi, *Alo, *Uhi, *Ulo, *Vhi, *Vlo, *hhi, *hlo;
    cudaGetSymbolAddress((void**)&Ahi, g_Ahi);
    cudaGetSymbolAddress((void**)&Alo, g_Alo);
    cudaGetSymbolAddress((void**)&Uhi, g_Uhi);
    cudaGetSymbolAddress((void**)&Ulo, g_Ulo);
    cudaGetSymbolAddress((void**)&Vhi, g_Vhi);
    cudaGetSymbolAddress((void**)&Vlo, g_Vlo);
    cudaGetSymbolAddress((void**)&hhi, g_hhi);
    cudaGetSymbolAddress((void**)&hlo, g_hlo);

    cudaFuncSetAttribute(lstm_persistent,
                         cudaFuncAttributeMaxDynamicSharedMemorySize, PERS_SMEM);

    // 0) bf16 hi/lo splits: A, U, V, h0
    const int nA4 = SS * BB * DD / 4;
    const int nU4 = G4H * DD / 4;
    const int nV4 = G4H * HH / 4;
    const int nH4 = BH / 4;
    split_bf16<<<nA4 / 256, 256>>>(layer_input, Ahi, Alo, nA4);
    split_bf16<<<nU4 / 256, 256>>>(U, Uhi, Ulo, nU4);
    split_bf16<<<nV4 / 256, 256>>>(V, Vhi, Vlo, nV4);
    split_bf16<<<nH4 / 256, 256>>>(h_t, hhi, hlo, nH4);

    // 1) HMMA input projection + bias
    dim3 gg(G4H / 128, (SS * BB) / 128);   // (32, 128)
    gemm_x_hmma<<<gg, 256>>>(Ahi, Alo, Uhi, Ulo, bih, bhh, Xp);

    // 2) persistent HMMA recurrence (all 512 steps)
    lstm_persistent<<<GRID, PTHREADS, PERS_SMEM>>>(
        Xp, c_t, Vhi, Vlo, hhi, hlo,
        all_h1, all_h2, all_c, h_f, c_f);
}